// round 5
// baseline (speedup 1.0000x reference)
#include <cuda_runtime.h>
#include <cuda_bf16.h>
#include <cstdint>

#define NMAX    50000
#define EMAX    800000
#define INDIM   100
#define D1      512
#define D2      256
#define D3      128
#define D4      200

// Scratch
__device__ float g_dinv[NMAX];
__device__ int   g_group[NMAX];
__device__ float g_gcnt[4];
__device__ float g_gsum[4 * D4];
__device__ int   g_cnt[NMAX];
__device__ int   g_fill[NMAX];
__device__ int   g_rowptr[NMAX + 1];
__device__ int   g_csr[EMAX];
__device__ float g_bufA[(size_t)NMAX * 256];
__device__ float g_bufB[(size_t)NMAX * 256];
__device__ float g_bufC[(size_t)NMAX * 512];

// ---------------------------------------------------------------------------
__global__ void zero_kernel(int M) {
    int i = blockIdx.x * blockDim.x + threadIdx.x;
    if (i < M) { g_cnt[i] = 0; g_fill[i] = 0; }
    if (i < 4 * D4) g_gsum[i] = 0.0f;
    if (i < 4) g_gcnt[i] = 0.0f;
}

__global__ void count_kernel(const int* __restrict__ ei, int E) {
    int e = blockIdx.x * blockDim.x + threadIdx.x;
    if (e >= E) return;
    atomicAdd(&g_cnt[ei[E + e]], 1);
}

// single-block chunked Hillis-Steele scan -> exclusive rowptr
__global__ void scan_kernel(int M) {
    __shared__ int buf[2][1024];
    __shared__ int carry;
    int t = threadIdx.x;
    if (t == 0) { carry = 0; g_rowptr[0] = 0; }
    __syncthreads();
    for (int base = 0; base < M; base += 1024) {
        int i = base + t;
        int v = (i < M) ? g_cnt[i] : 0;
        int sel = 0;
        buf[0][t] = v;
        __syncthreads();
        #pragma unroll
        for (int off = 1; off < 1024; off <<= 1) {
            int x = buf[sel][t];
            if (t >= off) x += buf[sel][t - off];
            buf[sel ^ 1][t] = x;
            sel ^= 1;
            __syncthreads();
        }
        if (i < M) g_rowptr[i + 1] = carry + buf[sel][t];
        int total = buf[sel][1023];
        __syncthreads();
        if (t == 0) carry += total;
        __syncthreads();
    }
}

__global__ void fill_kernel(const int* __restrict__ ei, int E) {
    int e = blockIdx.x * blockDim.x + threadIdx.x;
    if (e >= E) return;
    int d = ei[E + e];
    int pos = atomicAdd(&g_fill[d], 1);
    g_csr[g_rowptr[d] + pos] = ei[e];
}

// warp-per-node: coalesced group classification + dinv
__global__ void node_prep(const float* __restrict__ x, const float* __restrict__ nf, int M) {
    int warp = (blockIdx.x * blockDim.x + threadIdx.x) >> 5;
    int lane = threadIdx.x & 31;
    if (warp >= M) return;
    const float* row = x + (size_t)warp * INDIM;
    bool e0 = true, e1 = true, e2 = true;
    #pragma unroll
    for (int j = lane; j < INDIM; j += 32) {
        float a = row[j];
        e0 = e0 && (a == nf[j]);
        e1 = e1 && (a == nf[INDIM + j]);
        e2 = e2 && (a == nf[2 * INDIM + j]);
    }
    unsigned m = 0xFFFFFFFFu;
    bool a0 = __all_sync(m, e0);
    bool a1 = __all_sync(m, e1);
    bool a2 = __all_sync(m, e2);
    if (lane == 0) {
        int g = a0 ? 0 : (a1 ? 3 : (a2 ? 1 : 2));
        g_group[warp] = g;
        atomicAdd(&g_gcnt[g], 1.0f);
        g_dinv[warp] = rsqrtf((float)(g_rowptr[warp + 1] - g_rowptr[warp] + 1));
    }
}

// bufA = x * dinv[row]
__global__ void scale_x(const float* __restrict__ x, float* __restrict__ out, int M) {
    size_t idx = (size_t)blockIdx.x * blockDim.x + threadIdx.x;
    size_t total = (size_t)M * INDIM;
    if (idx >= total) return;
    int r = (int)(idx / INDIM);
    out[idx] = x[idx] * g_dinv[r];
}

// ---------------------------------------------------------------------------
// Gather aggregation: one warp per dst node.
// epi 0: out = dinv*acc ; epi 1: relu(dinv*acc+b) ; epi 2: relu(dinv*acc+b)*dinv
__global__ __launch_bounds__(256) void gather_kernel(
    const float* __restrict__ Hs, float* __restrict__ out,
    const float* __restrict__ bias, int M, int dim, int epi)
{
    int warp = (blockIdx.x * blockDim.x + threadIdx.x) >> 5;
    int lane = threadIdx.x & 31;
    if (warp >= M) return;
    int d4 = dim >> 2;
    int c0 = lane, c1 = lane + 32;
    bool p0 = c0 < d4, p1 = c1 < d4;
    int start = g_rowptr[warp], end = g_rowptr[warp + 1];
    float di = g_dinv[warp];

    float4 a0 = make_float4(0.f, 0.f, 0.f, 0.f);
    float4 a1 = make_float4(0.f, 0.f, 0.f, 0.f);
    const float* self = Hs + (size_t)warp * dim;
    if (p0) a0 = *(const float4*)(self + c0 * 4);
    if (p1) a1 = *(const float4*)(self + c1 * 4);

    int j = start;
    for (; j + 4 <= end; j += 4) {
        int s0 = g_csr[j], s1 = g_csr[j + 1], s2 = g_csr[j + 2], s3 = g_csr[j + 3];
        const float* r0 = Hs + (size_t)s0 * dim;
        const float* r1 = Hs + (size_t)s1 * dim;
        const float* r2 = Hs + (size_t)s2 * dim;
        const float* r3 = Hs + (size_t)s3 * dim;
        if (p0) {
            float4 v0 = *(const float4*)(r0 + c0 * 4);
            float4 v1 = *(const float4*)(r1 + c0 * 4);
            float4 v2 = *(const float4*)(r2 + c0 * 4);
            float4 v3 = *(const float4*)(r3 + c0 * 4);
            a0.x += v0.x + v1.x + v2.x + v3.x;
            a0.y += v0.y + v1.y + v2.y + v3.y;
            a0.z += v0.z + v1.z + v2.z + v3.z;
            a0.w += v0.w + v1.w + v2.w + v3.w;
        }
        if (p1) {
            float4 v0 = *(const float4*)(r0 + c1 * 4);
            float4 v1 = *(const float4*)(r1 + c1 * 4);
            float4 v2 = *(const float4*)(r2 + c1 * 4);
            float4 v3 = *(const float4*)(r3 + c1 * 4);
            a1.x += v0.x + v1.x + v2.x + v3.x;
            a1.y += v0.y + v1.y + v2.y + v3.y;
            a1.z += v0.z + v1.z + v2.z + v3.z;
            a1.w += v0.w + v1.w + v2.w + v3.w;
        }
    }
    for (; j < end; j++) {
        int s = g_csr[j];
        const float* r = Hs + (size_t)s * dim;
        if (p0) {
            float4 v = *(const float4*)(r + c0 * 4);
            a0.x += v.x; a0.y += v.y; a0.z += v.z; a0.w += v.w;
        }
        if (p1) {
            float4 v = *(const float4*)(r + c1 * 4);
            a1.x += v.x; a1.y += v.y; a1.z += v.z; a1.w += v.w;
        }
    }

    float* orow = out + (size_t)warp * dim;
    if (p0) {
        float4 v;
        v.x = di * a0.x; v.y = di * a0.y; v.z = di * a0.z; v.w = di * a0.w;
        if (epi >= 1) {
            float4 b = *(const float4*)(bias + c0 * 4);
            v.x = fmaxf(v.x + b.x, 0.f); v.y = fmaxf(v.y + b.y, 0.f);
            v.z = fmaxf(v.z + b.z, 0.f); v.w = fmaxf(v.w + b.w, 0.f);
            if (epi == 2) { v.x *= di; v.y *= di; v.z *= di; v.w *= di; }
        }
        *(float4*)(orow + c0 * 4) = v;
    }
    if (p1) {
        float4 v;
        v.x = di * a1.x; v.y = di * a1.y; v.z = di * a1.z; v.w = di * a1.w;
        if (epi >= 1) {
            float4 b = *(const float4*)(bias + c1 * 4);
            v.x = fmaxf(v.x + b.x, 0.f); v.y = fmaxf(v.y + b.y, 0.f);
            v.z = fmaxf(v.z + b.z, 0.f); v.w = fmaxf(v.w + b.w, 0.f);
            if (epi == 2) { v.x *= di; v.y *= di; v.z *= di; v.w *= di; }
        }
        *(float4*)(orow + c1 * 4) = v;
    }
}

// ---------------------------------------------------------------------------
// Split-BF16 tensor-core GEMM (fp32-class accuracy).
// Block tile 128x128, 8 warps (warp tile 32x64), m16n8k16 bf16 MMA.
// a = ahi + alo (bf16 split); 3-term: ahi*bhi + ahi*blo + alo*bhi.
// Smem holds fragments in MMA-native order -> vector LDS in mainloop.
// epi 0: C = relu(acc + bias) ; epi 1: C = dinv[row] * acc

__device__ __forceinline__ uint32_t pack_bf16(float x, float y) {
    __nv_bfloat16 bx = __float2bfloat16_rn(x);
    __nv_bfloat16 by = __float2bfloat16_rn(y);
    return (uint32_t)__bfloat16_as_ushort(bx) |
           ((uint32_t)__bfloat16_as_ushort(by) << 16);
}

__device__ __forceinline__ void bf16_split(float v, float& hi, float& lo) {
    __nv_bfloat16 h = __float2bfloat16_rn(v);
    hi = __bfloat162float(h);
    lo = v - hi;
}

__device__ __forceinline__ void mma_bf16(float* c, const uint32_t* a, const uint32_t* b) {
    asm volatile(
        "mma.sync.aligned.m16n8k16.row.col.f32.bf16.bf16.f32 "
        "{%0,%1,%2,%3}, {%4,%5,%6,%7}, {%8,%9}, {%0,%1,%2,%3};\n"
        : "+f"(c[0]), "+f"(c[1]), "+f"(c[2]), "+f"(c[3])
        : "r"(a[0]), "r"(a[1]), "r"(a[2]), "r"(a[3]),
          "r"(b[0]), "r"(b[1]));
}

__global__ __launch_bounds__(256) void gemm_bf16s(
    const float* __restrict__ A, const float* __restrict__ W,
    const float* __restrict__ bias, float* __restrict__ C,
    int M, int K, int N, int epi)
{
    // Afrag[rowblk16][lane][reg]: regs 0-3 = hi a0..a3, 4-7 = lo a0..a3
    // Bfrag[colblk8][lane][reg]:  regs 0-1 = hi b0..b1, 2-3 = lo b0..b1
    __shared__ uint32_t Afrag[8][32][8];
    __shared__ uint32_t Bfrag[16][32][4];

    int tid = threadIdx.x;
    int r0 = blockIdx.x * 128;
    int n0 = blockIdx.y * 128;
    int wid = tid >> 5, lane = tid & 31;
    int g = lane >> 2, t = lane & 3;

    int wrb = (wid >> 1) * 2;   // warp row-block base (16-row units)
    int wcb = (wid & 1) * 8;    // warp col-block base (8-col units)

    // A loader: thread -> (row, k-half)
    int la_r = tid >> 1;        // 0..127
    int la_h = tid & 1;         // k 8*h .. 8*h+7
    // B loader: thread -> (k-pair, 4 cols)
    int lb_k2 = tid >> 5;       // 0..7  (k = 2*k2, 2*k2+1)
    int lb_c0 = (tid & 31) * 4; // col base 0..124

    float acc[2][8][4];
    #pragma unroll
    for (int mi = 0; mi < 2; mi++)
        #pragma unroll
        for (int ni = 0; ni < 8; ni++)
            #pragma unroll
            for (int q = 0; q < 4; q++) acc[mi][ni][q] = 0.0f;

    int nk = (K + 15) >> 4;
    for (int it = 0; it < nk; it++) {
        int kt = it << 4;

        // ---- global loads into registers
        float av[8];
        {
            int gr = r0 + la_r;
            int kg = kt + la_h * 8;
            #pragma unroll
            for (int j = 0; j < 8; j++) av[j] = 0.f;
            if (gr < M) {
                const float* ap = A + (size_t)gr * K;
                if (kg + 7 < K) {
                    float4 v0 = *(const float4*)(ap + kg);
                    float4 v1 = *(const float4*)(ap + kg + 4);
                    av[0] = v0.x; av[1] = v0.y; av[2] = v0.z; av[3] = v0.w;
                    av[4] = v1.x; av[5] = v1.y; av[6] = v1.z; av[7] = v1.w;
                } else {
                    #pragma unroll
                    for (int j = 0; j < 8; j++)
                        if (kg + j < K) av[j] = ap[kg + j];
                }
            }
        }
        float bv0[4], bv1[4];
        {
            int k0 = kt + lb_k2 * 2;
            int nb = n0 + lb_c0;
            #pragma unroll
            for (int j = 0; j < 4; j++) { bv0[j] = 0.f; bv1[j] = 0.f; }
            if (k0 < K) {
                const float* wp = W + (size_t)k0 * N;
                if (nb + 3 < N) {
                    float4 v = *(const float4*)(wp + nb);
                    bv0[0] = v.x; bv0[1] = v.y; bv0[2] = v.z; bv0[3] = v.w;
                } else {
                    #pragma unroll
                    for (int j = 0; j < 4; j++) if (nb + j < N) bv0[j] = wp[nb + j];
                }
            }
            if (k0 + 1 < K) {
                const float* wp = W + (size_t)(k0 + 1) * N;
                if (nb + 3 < N) {
                    float4 v = *(const float4*)(wp + nb);
                    bv1[0] = v.x; bv1[1] = v.y; bv1[2] = v.z; bv1[3] = v.w;
                } else {
                    #pragma unroll
                    for (int j = 0; j < 4; j++) if (nb + j < N) bv1[j] = wp[nb + j];
                }
            }
        }

        __syncthreads();  // previous stage's compute done

        // ---- write A fragments (split hi/lo)
        {
            int rb = la_r >> 4, rr = la_r & 15;
            int regbase = (rr >> 3) + 2 * la_h;   // 0..3
            int lanebase = (rr & 7) * 4;
            #pragma unroll
            for (int j = 0; j < 4; j++) {
                float hx, lx, hy, ly;
                bf16_split(av[2 * j], hx, lx);
                bf16_split(av[2 * j + 1], hy, ly);
                Afrag[rb][lanebase + j][regbase]     = pack_bf16(hx, hy);
                Afrag[rb][lanebase + j][regbase + 4] = pack_bf16(lx, ly);
            }
        }
        // ---- write B fragments (split hi/lo)
        {
            int reg = lb_k2 >> 2;     // 0 or 1
            int tt = lb_k2 & 3;
            #pragma unroll
            for (int cc = 0; cc < 4; cc++) {
                int c = lb_c0 + cc;
                int cb = c >> 3, gg = c & 7;
                float hx, lx, hy, ly;
                bf16_split(bv0[cc], hx, lx);
                bf16_split(bv1[cc], hy, ly);
                Bfrag[cb][gg * 4 + tt][reg]     = pack_bf16(hx, hy);
                Bfrag[cb][gg * 4 + tt][reg + 2] = pack_bf16(lx, ly);
            }
        }
        __syncthreads();

        // ---- compute: vectorized fragment loads + MMAs
        uint32_t Ah[2][4], Al[2][4];
        #pragma unroll
        for (int mi = 0; mi < 2; mi++) {
            uint4 h = *(const uint4*)&Afrag[wrb + mi][lane][0];
            Ah[mi][0] = h.x; Ah[mi][1] = h.y; Ah[mi][2] = h.z; Ah[mi][3] = h.w;
            uint4 l = *(const uint4*)&Afrag[wrb + mi][lane][4];
            Al[mi][0] = l.x; Al[mi][1] = l.y; Al[mi][2] = l.z; Al[mi][3] = l.w;
        }
        #pragma unroll
        for (int ni = 0; ni < 8; ni++) {
            uint4 bb = *(const uint4*)&Bfrag[wcb + ni][lane][0];
            uint32_t Bh[2] = {bb.x, bb.y};
            uint32_t Bl[2] = {bb.z, bb.w};
            #pragma unroll
            for (int mi = 0; mi < 2; mi++) {
                mma_bf16(acc[mi][ni], Ah[mi], Bh);
                mma_bf16(acc[mi][ni], Ah[mi], Bl);
                mma_bf16(acc[mi][ni], Al[mi], Bh);
            }
        }
    }

    // ---- epilogue
    #pragma unroll
    for (int mi = 0; mi < 2; mi++) {
        int row0 = r0 + (wid >> 1) * 32 + mi * 16 + g;
        int row1 = row0 + 8;
        float d0 = 0.f, d1 = 0.f;
        if (epi == 1) {
            if (row0 < M) d0 = g_dinv[row0];
            if (row1 < M) d1 = g_dinv[row1];
        }
        #pragma unroll
        for (int ni = 0; ni < 8; ni++) {
            int col = n0 + (wid & 1) * 64 + ni * 8 + 2 * t;
            float* c = acc[mi][ni];
            if (epi == 0) {
                float bx = (col < N) ? bias[col] : 0.f;
                float by = (col + 1 < N) ? bias[col + 1] : 0.f;
                if (row0 < M) {
                    if (col < N)     C[(size_t)row0 * N + col]     = fmaxf(c[0] + bx, 0.f);
                    if (col + 1 < N) C[(size_t)row0 * N + col + 1] = fmaxf(c[1] + by, 0.f);
                }
                if (row1 < M) {
                    if (col < N)     C[(size_t)row1 * N + col]     = fmaxf(c[2] + bx, 0.f);
                    if (col + 1 < N) C[(size_t)row1 * N + col + 1] = fmaxf(c[3] + by, 0.f);
                }
            } else {
                if (row0 < M) {
                    if (col < N)     C[(size_t)row0 * N + col]     = d0 * c[0];
                    if (col + 1 < N) C[(size_t)row0 * N + col + 1] = d0 * c[1];
                }
                if (row1 < M) {
                    if (col < N)     C[(size_t)row1 * N + col]     = d1 * c[2];
                    if (col + 1 < N) C[(size_t)row1 * N + col + 1] = d1 * c[3];
                }
            }
        }
    }
}

// ---------------------------------------------------------------------------
__global__ void group_reduce(const float* __restrict__ out4, int M) {
    __shared__ float s[4 * D4];
    for (int i = threadIdx.x; i < 4 * D4; i += blockDim.x) s[i] = 0.0f;
    __syncthreads();
    int base = blockIdx.x * 256;
    for (int n = 0; n < 256; n++) {
        int node = base + n;
        if (node >= M) break;
        int g = g_group[node];
        const float* row = out4 + (size_t)node * D4;
        for (int c = threadIdx.x; c < D4; c += blockDim.x)
            s[g * D4 + c] += row[c];
    }
    __syncthreads();
    for (int i = threadIdx.x; i < 4 * D4; i += blockDim.x)
        if (s[i] != 0.0f) atomicAdd(&g_gsum[i], s[i]);
}

__global__ void final_out(float* __restrict__ out) {
    int i = blockIdx.x * blockDim.x + threadIdx.x;
    if (i >= 4 * D4) return;
    float c = g_gcnt[i / D4];
    out[i] = (c > 0.0f) ? g_gsum[i] / c : 0.0f;
}

// ---------------------------------------------------------------------------
static inline int ceil_div(long long a, long long b) { return (int)((a + b - 1) / b); }

extern "C" void kernel_launch(void* const* d_in, const int* in_sizes, int n_in,
                              void* d_out, int out_size) {
    const float* x  = (const float*)d_in[0];
    const float* nf = (const float*)d_in[1];
    const int*   ei = (const int*)d_in[2];
    const float* W1 = (const float*)d_in[3];
    const float* b1 = (const float*)d_in[4];
    const float* W2 = (const float*)d_in[5];
    const float* b2 = (const float*)d_in[6];
    const float* W3 = (const float*)d_in[7];
    const float* b3 = (const float*)d_in[8];
    const float* W4 = (const float*)d_in[9];
    const float* b4 = (const float*)d_in[10];
    float* out = (float*)d_out;

    int M = in_sizes[0] / INDIM;     // 50000
    int E = in_sizes[2] / 2;         // 800000

    float *bufA, *bufB, *bufC;
    cudaGetSymbolAddress((void**)&bufA, g_bufA);
    cudaGetSymbolAddress((void**)&bufB, g_bufB);
    cudaGetSymbolAddress((void**)&bufC, g_bufC);

    const int T = 256;

    // CSR build + node metadata
    zero_kernel<<<ceil_div(M, T), T>>>(M);
    count_kernel<<<ceil_div(E, T), T>>>(ei, E);
    scan_kernel<<<1, 1024>>>(M);
    fill_kernel<<<ceil_div(E, T), T>>>(ei, E);
    node_prep<<<ceil_div(M, 8), T>>>(x, nf, M);

    int gblocks = ceil_div(M, 8);  // 8 warps per block

    // ---- Layer 1
    scale_x<<<ceil_div((long long)M * INDIM, T), T>>>(x, bufA, M);
    gather_kernel<<<gblocks, 256>>>(bufA, bufB, nullptr, M, INDIM, 0);
    {
        dim3 g(ceil_div(M, 128), ceil_div(D1, 128));
        gemm_bf16s<<<g, 256>>>(bufB, W1, b1, bufC, M, INDIM, D1, 0);
    }

    // ---- Layer 2
    {
        dim3 g(ceil_div(M, 128), ceil_div(D2, 128));
        gemm_bf16s<<<g, 256>>>(bufC, W2, nullptr, bufA, M, D1, D2, 1);
    }
    gather_kernel<<<gblocks, 256>>>(bufA, bufB, b2, M, D2, 1);

    // ---- Layer 3
    {
        dim3 g(ceil_div(M, 128), ceil_div(D3, 128));
        gemm_bf16s<<<g, 256>>>(bufB, W3, nullptr, bufA, M, D2, D3, 1);
    }
    gather_kernel<<<gblocks, 256>>>(bufA, bufB, b3, M, D3, 2);

    // ---- Layer 4
    gather_kernel<<<gblocks, 256>>>(bufB, bufA, nullptr, M, D3, 0);
    {
        dim3 g(ceil_div(M, 128), ceil_div(D4, 128));
        gemm_bf16s<<<g, 256>>>(bufA, W4, b4, bufC, M, D3, D4, 0);
    }

    // ---- grouped mean pooling
    group_reduce<<<ceil_div(M, 256), 128>>>(bufC, M);
    final_out<<<ceil_div(4 * D4, T), T>>>(out);
}

// round 6
// speedup vs baseline: 1.3902x; 1.3902x over previous
#include <cuda_runtime.h>
#include <cuda_bf16.h>
#include <cstdint>

#define NMAX    50000
#define EMAX    800000
#define INDIM   100
#define D1      512
#define D2      256
#define D3      128
#define D4      200

// Scratch
__device__ float g_dinv[NMAX];
__device__ int   g_group[NMAX];
__device__ float g_gcnt[4];
__device__ float g_gsum[4 * D4];
__device__ int   g_cnt[NMAX];
__device__ int   g_fill[NMAX];
__device__ int   g_rowptr[NMAX + 1];
__device__ int   g_csr[EMAX];
__device__ float g_bufA[(size_t)NMAX * 256];
__device__ float g_bufB[(size_t)NMAX * 256];
__device__ float g_bufC[(size_t)NMAX * 512];

// ---------------------------------------------------------------------------
__global__ void zero_kernel(int M) {
    int i = blockIdx.x * blockDim.x + threadIdx.x;
    if (i < M) { g_cnt[i] = 0; g_fill[i] = 0; }
    if (i < 4 * D4) g_gsum[i] = 0.0f;
    if (i < 4) g_gcnt[i] = 0.0f;
}

__global__ void count_kernel(const int* __restrict__ ei, int E) {
    int e = blockIdx.x * blockDim.x + threadIdx.x;
    if (e >= E) return;
    atomicAdd(&g_cnt[ei[E + e]], 1);
}

// single-block chunked Hillis-Steele scan -> exclusive rowptr
__global__ void scan_kernel(int M) {
    __shared__ int buf[2][1024];
    __shared__ int carry;
    int t = threadIdx.x;
    if (t == 0) { carry = 0; g_rowptr[0] = 0; }
    __syncthreads();
    for (int base = 0; base < M; base += 1024) {
        int i = base + t;
        int v = (i < M) ? g_cnt[i] : 0;
        int sel = 0;
        buf[0][t] = v;
        __syncthreads();
        #pragma unroll
        for (int off = 1; off < 1024; off <<= 1) {
            int x = buf[sel][t];
            if (t >= off) x += buf[sel][t - off];
            buf[sel ^ 1][t] = x;
            sel ^= 1;
            __syncthreads();
        }
        if (i < M) g_rowptr[i + 1] = carry + buf[sel][t];
        int total = buf[sel][1023];
        __syncthreads();
        if (t == 0) carry += total;
        __syncthreads();
    }
}

// fused: fill CSR (first nFill blocks) + node classification/dinv (rest)
__global__ void fillprep_kernel(const int* __restrict__ ei,
                                const float* __restrict__ x,
                                const float* __restrict__ nf,
                                int E, int M, int nFill) {
    if ((int)blockIdx.x < nFill) {
        int e = blockIdx.x * blockDim.x + threadIdx.x;
        if (e >= E) return;
        int d = ei[E + e];
        int pos = atomicAdd(&g_fill[d], 1);
        g_csr[g_rowptr[d] + pos] = ei[e];
    } else {
        int warp = ((blockIdx.x - nFill) * blockDim.x + threadIdx.x) >> 5;
        int lane = threadIdx.x & 31;
        if (warp >= M) return;
        const float* row = x + (size_t)warp * INDIM;
        bool e0 = true, e1 = true, e2 = true;
        #pragma unroll
        for (int j = lane; j < INDIM; j += 32) {
            float a = row[j];
            e0 = e0 && (a == nf[j]);
            e1 = e1 && (a == nf[INDIM + j]);
            e2 = e2 && (a == nf[2 * INDIM + j]);
        }
        unsigned m = 0xFFFFFFFFu;
        bool a0 = __all_sync(m, e0);
        bool a1 = __all_sync(m, e1);
        bool a2 = __all_sync(m, e2);
        if (lane == 0) {
            int g = a0 ? 0 : (a1 ? 3 : (a2 ? 1 : 2));
            g_group[warp] = g;
            atomicAdd(&g_gcnt[g], 1.0f);
            g_dinv[warp] = rsqrtf((float)(g_rowptr[warp + 1] - g_rowptr[warp] + 1));
        }
    }
}

// ---------------------------------------------------------------------------
// Gather aggregation: one warp per dst node.
// scale_src: multiply each source row (and self) by dinv[src] while loading.
// epi 0: out = dinv*acc ; epi 1: relu(dinv*acc+b) ; epi 2: relu(dinv*acc+b)*dinv
__global__ __launch_bounds__(256) void gather_kernel(
    const float* __restrict__ Hs, float* __restrict__ out,
    const float* __restrict__ bias, int M, int dim, int epi, int scale_src)
{
    int warp = (blockIdx.x * blockDim.x + threadIdx.x) >> 5;
    int lane = threadIdx.x & 31;
    if (warp >= M) return;
    int d4 = dim >> 2;
    int c0 = lane, c1 = lane + 32;
    bool p0 = c0 < d4, p1 = c1 < d4;
    int start = g_rowptr[warp], end = g_rowptr[warp + 1];
    float di = g_dinv[warp];

    float4 a0 = make_float4(0.f, 0.f, 0.f, 0.f);
    float4 a1 = make_float4(0.f, 0.f, 0.f, 0.f);
    const float* self = Hs + (size_t)warp * dim;
    float selfs = scale_src ? di : 1.0f;
    if (p0) {
        float4 v = *(const float4*)(self + c0 * 4);
        a0.x = selfs * v.x; a0.y = selfs * v.y; a0.z = selfs * v.z; a0.w = selfs * v.w;
    }
    if (p1) {
        float4 v = *(const float4*)(self + c1 * 4);
        a1.x = selfs * v.x; a1.y = selfs * v.y; a1.z = selfs * v.z; a1.w = selfs * v.w;
    }

    int j = start;
    for (; j + 4 <= end; j += 4) {
        int s0 = g_csr[j], s1 = g_csr[j + 1], s2 = g_csr[j + 2], s3 = g_csr[j + 3];
        float d0 = 1.f, d1 = 1.f, d2 = 1.f, d3 = 1.f;
        if (scale_src) { d0 = g_dinv[s0]; d1 = g_dinv[s1]; d2 = g_dinv[s2]; d3 = g_dinv[s3]; }
        const float* r0 = Hs + (size_t)s0 * dim;
        const float* r1 = Hs + (size_t)s1 * dim;
        const float* r2 = Hs + (size_t)s2 * dim;
        const float* r3 = Hs + (size_t)s3 * dim;
        if (p0) {
            float4 v0 = *(const float4*)(r0 + c0 * 4);
            float4 v1 = *(const float4*)(r1 + c0 * 4);
            float4 v2 = *(const float4*)(r2 + c0 * 4);
            float4 v3 = *(const float4*)(r3 + c0 * 4);
            a0.x += d0 * v0.x + d1 * v1.x + d2 * v2.x + d3 * v3.x;
            a0.y += d0 * v0.y + d1 * v1.y + d2 * v2.y + d3 * v3.y;
            a0.z += d0 * v0.z + d1 * v1.z + d2 * v2.z + d3 * v3.z;
            a0.w += d0 * v0.w + d1 * v1.w + d2 * v2.w + d3 * v3.w;
        }
        if (p1) {
            float4 v0 = *(const float4*)(r0 + c1 * 4);
            float4 v1 = *(const float4*)(r1 + c1 * 4);
            float4 v2 = *(const float4*)(r2 + c1 * 4);
            float4 v3 = *(const float4*)(r3 + c1 * 4);
            a1.x += d0 * v0.x + d1 * v1.x + d2 * v2.x + d3 * v3.x;
            a1.y += d0 * v0.y + d1 * v1.y + d2 * v2.y + d3 * v3.y;
            a1.z += d0 * v0.z + d1 * v1.z + d2 * v2.z + d3 * v3.z;
            a1.w += d0 * v0.w + d1 * v1.w + d2 * v2.w + d3 * v3.w;
        }
    }
    for (; j < end; j++) {
        int s = g_csr[j];
        float ds = scale_src ? g_dinv[s] : 1.0f;
        const float* r = Hs + (size_t)s * dim;
        if (p0) {
            float4 v = *(const float4*)(r + c0 * 4);
            a0.x += ds * v.x; a0.y += ds * v.y; a0.z += ds * v.z; a0.w += ds * v.w;
        }
        if (p1) {
            float4 v = *(const float4*)(r + c1 * 4);
            a1.x += ds * v.x; a1.y += ds * v.y; a1.z += ds * v.z; a1.w += ds * v.w;
        }
    }

    float* orow = out + (size_t)warp * dim;
    if (p0) {
        float4 v;
        v.x = di * a0.x; v.y = di * a0.y; v.z = di * a0.z; v.w = di * a0.w;
        if (epi >= 1) {
            float4 b = *(const float4*)(bias + c0 * 4);
            v.x = fmaxf(v.x + b.x, 0.f); v.y = fmaxf(v.y + b.y, 0.f);
            v.z = fmaxf(v.z + b.z, 0.f); v.w = fmaxf(v.w + b.w, 0.f);
            if (epi == 2) { v.x *= di; v.y *= di; v.z *= di; v.w *= di; }
        }
        *(float4*)(orow + c0 * 4) = v;
    }
    if (p1) {
        float4 v;
        v.x = di * a1.x; v.y = di * a1.y; v.z = di * a1.z; v.w = di * a1.w;
        if (epi >= 1) {
            float4 b = *(const float4*)(bias + c1 * 4);
            v.x = fmaxf(v.x + b.x, 0.f); v.y = fmaxf(v.y + b.y, 0.f);
            v.z = fmaxf(v.z + b.z, 0.f); v.w = fmaxf(v.w + b.w, 0.f);
            if (epi == 2) { v.x *= di; v.y *= di; v.z *= di; v.w *= di; }
        }
        *(float4*)(orow + c1 * 4) = v;
    }
}

// ---------------------------------------------------------------------------
// Split-BF16 tensor-core GEMM, ldmatrix + XOR swizzle, K-stage 32.
// Block 128x128, 8 warps, warp tile 32x64, m16n8k16.
// a = ahi + alo; 3-term: ahi*bhi + ahi*blo + alo*bhi.
// epi 0: C = relu(acc + bias) ; epi 1: C = dinv[row] * acc

__device__ __forceinline__ uint32_t pack_bf16(float x, float y) {
    __nv_bfloat16 bx = __float2bfloat16_rn(x);
    __nv_bfloat16 by = __float2bfloat16_rn(y);
    return (uint32_t)__bfloat16_as_ushort(bx) |
           ((uint32_t)__bfloat16_as_ushort(by) << 16);
}

__device__ __forceinline__ void bf16_split(float v, float& hi, float& lo) {
    __nv_bfloat16 h = __float2bfloat16_rn(v);
    hi = __bfloat162float(h);
    lo = v - hi;
}

__device__ __forceinline__ void mma_bf16(float* c, const uint32_t* a, const uint32_t* b) {
    asm volatile(
        "mma.sync.aligned.m16n8k16.row.col.f32.bf16.bf16.f32 "
        "{%0,%1,%2,%3}, {%4,%5,%6,%7}, {%8,%9}, {%0,%1,%2,%3};\n"
        : "+f"(c[0]), "+f"(c[1]), "+f"(c[2]), "+f"(c[3])
        : "r"(a[0]), "r"(a[1]), "r"(a[2]), "r"(a[3]),
          "r"(b[0]), "r"(b[1]));
}

__device__ __forceinline__ void ldsm_x4(uint32_t* r, uint32_t addr) {
    asm volatile("ldmatrix.sync.aligned.m8n8.x4.shared.b16 {%0,%1,%2,%3}, [%4];"
                 : "=r"(r[0]), "=r"(r[1]), "=r"(r[2]), "=r"(r[3]) : "r"(addr));
}
__device__ __forceinline__ void ldsm_x4_t(uint32_t* r, uint32_t addr) {
    asm volatile("ldmatrix.sync.aligned.m8n8.x4.trans.shared.b16 {%0,%1,%2,%3}, [%4];"
                 : "=r"(r[0]), "=r"(r[1]), "=r"(r[2]), "=r"(r[3]) : "r"(addr));
}

__global__ __launch_bounds__(256) void gemm_bf16s(
    const float* __restrict__ A, const float* __restrict__ W,
    const float* __restrict__ bias, float* __restrict__ C,
    int M, int K, int N, int epi)
{
    // A tiles: 128 rows x 32 k (bf16) = 64B/row = 4 chunks of 16B, swizzle c^((m>>1)&3)
    // B tiles: 32 k-rows x 128 n (bf16) = 256B/row = 16 chunks, swizzle c^(k&7)
    __shared__ __align__(16) __nv_bfloat16 Ah[128 * 32], Al[128 * 32];
    __shared__ __align__(16) __nv_bfloat16 Bh[32 * 128], Bl[32 * 128];

    int tid = threadIdx.x;
    int r0 = blockIdx.x * 128;
    int n0 = blockIdx.y * 128;
    int wid = tid >> 5, lane = tid & 31;
    int gq = lane >> 2, tq = lane & 3;
    int mwarp = (wid >> 1) * 32;
    int nwarp = (wid & 1) * 64;

    // loaders
    int a_row = tid >> 1, a_h = tid & 1;     // row 0..127, k-half 16*a_h
    int b_k = tid >> 3, b_g = tid & 7;       // k-row 0..31, col group 16*b_g

    float acc[2][8][4];
    #pragma unroll
    for (int mi = 0; mi < 2; mi++)
        #pragma unroll
        for (int ni = 0; ni < 8; ni++)
            #pragma unroll
            for (int q = 0; q < 4; q++) acc[mi][ni][q] = 0.0f;

    uint32_t Ah_base = (uint32_t)__cvta_generic_to_shared(Ah);
    uint32_t Al_base = (uint32_t)__cvta_generic_to_shared(Al);
    uint32_t Bh_base = (uint32_t)__cvta_generic_to_shared(Bh);
    uint32_t Bl_base = (uint32_t)__cvta_generic_to_shared(Bl);

    int nk = (K + 31) >> 5;
    float aR[16], bR[16];

    // ---- global prefetch for stage `it` into aR/bR
    auto load_g = [&](int it) {
        int kt = it * 32;
        {
            int gr = r0 + a_row;
            const float* ap = A + (size_t)gr * K;
            #pragma unroll
            for (int q = 0; q < 4; q++) {
                int kg = kt + a_h * 16 + q * 4;
                float4 v = make_float4(0.f, 0.f, 0.f, 0.f);
                if (gr < M && kg < K) v = *(const float4*)(ap + kg);
                aR[q * 4 + 0] = v.x; aR[q * 4 + 1] = v.y;
                aR[q * 4 + 2] = v.z; aR[q * 4 + 3] = v.w;
            }
        }
        {
            int kb = kt + b_k;
            const float* wp = W + (size_t)kb * N;
            #pragma unroll
            for (int q = 0; q < 4; q++) {
                int nb = n0 + b_g * 16 + q * 4;
                float4 v = make_float4(0.f, 0.f, 0.f, 0.f);
                if (kb < K && nb < N) v = *(const float4*)(wp + nb);
                bR[q * 4 + 0] = v.x; bR[q * 4 + 1] = v.y;
                bR[q * 4 + 2] = v.z; bR[q * 4 + 3] = v.w;
            }
        }
    };

    load_g(0);

    for (int it = 0; it < nk; it++) {
        __syncthreads();   // previous compute finished (no-op on it=0)

        // ---- write aR/bR to smem (split hi/lo, swizzled chunks)
        #pragma unroll
        for (int j = 0; j < 2; j++) {
            float h0, l0, h1, l1, h2, l2, h3, l3, h4, l4, h5, l5, h6, l6, h7, l7;
            bf16_split(aR[j*8+0], h0, l0); bf16_split(aR[j*8+1], h1, l1);
            bf16_split(aR[j*8+2], h2, l2); bf16_split(aR[j*8+3], h3, l3);
            bf16_split(aR[j*8+4], h4, l4); bf16_split(aR[j*8+5], h5, l5);
            bf16_split(aR[j*8+6], h6, l6); bf16_split(aR[j*8+7], h7, l7);
            uint4 hv = make_uint4(pack_bf16(h0,h1), pack_bf16(h2,h3),
                                  pack_bf16(h4,h5), pack_bf16(h6,h7));
            uint4 lv = make_uint4(pack_bf16(l0,l1), pack_bf16(l2,l3),
                                  pack_bf16(l4,l5), pack_bf16(l6,l7));
            int unit = a_row * 4 + ((2 * a_h + j) ^ ((a_row >> 1) & 3));
            ((uint4*)Ah)[unit] = hv;
            ((uint4*)Al)[unit] = lv;
        }
        #pragma unroll
        for (int j = 0; j < 2; j++) {
            float h0, l0, h1, l1, h2, l2, h3, l3, h4, l4, h5, l5, h6, l6, h7, l7;
            bf16_split(bR[j*8+0], h0, l0); bf16_split(bR[j*8+1], h1, l1);
            bf16_split(bR[j*8+2], h2, l2); bf16_split(bR[j*8+3], h3, l3);
            bf16_split(bR[j*8+4], h4, l4); bf16_split(bR[j*8+5], h5, l5);
            bf16_split(bR[j*8+6], h6, l6); bf16_split(bR[j*8+7], h7, l7);
            uint4 hv = make_uint4(pack_bf16(h0,h1), pack_bf16(h2,h3),
                                  pack_bf16(h4,h5), pack_bf16(h6,h7));
            uint4 lv = make_uint4(pack_bf16(l0,l1), pack_bf16(l2,l3),
                                  pack_bf16(l4,l5), pack_bf16(l6,l7));
            int unit = b_k * 16 + ((2 * b_g + j) ^ (b_k & 7));
            ((uint4*)Bh)[unit] = hv;
            ((uint4*)Bl)[unit] = lv;
        }
        __syncthreads();

        // ---- prefetch next stage (LDG latency hides under MMAs)
        if (it + 1 < nk) load_g(it + 1);

        // ---- compute: two k16 steps
        #pragma unroll
        for (int ks = 0; ks < 32; ks += 16) {
            uint32_t Ahf[2][4], Alf[2][4];
            #pragma unroll
            for (int mi = 0; mi < 2; mi++) {
                int mrow = mwarp + mi * 16 + (lane & 15);
                int chunk = (ks >> 3) + (lane >> 4);
                int unit = mrow * 4 + (chunk ^ ((mrow >> 1) & 3));
                ldsm_x4(Ahf[mi], Ah_base + unit * 16);
                ldsm_x4(Alf[mi], Al_base + unit * 16);
            }
            #pragma unroll
            for (int p = 0; p < 4; p++) {
                int nbase = nwarp + p * 16;
                int krow = ks + (lane & 7) + ((lane >> 3) & 1) * 8;
                int chunk = (nbase >> 3) + (lane >> 4);
                int unit = krow * 16 + (chunk ^ (krow & 7));
                uint32_t bh[4], bl[4];
                ldsm_x4_t(bh, Bh_base + unit * 16);
                ldsm_x4_t(bl, Bl_base + unit * 16);
                #pragma unroll
                for (int half = 0; half < 2; half++) {
                    int ni = 2 * p + half;
                    uint32_t* Bhf = bh + 2 * half;
                    uint32_t* Blf = bl + 2 * half;
                    #pragma unroll
                    for (int mi = 0; mi < 2; mi++) {
                        mma_bf16(acc[mi][ni], Ahf[mi], Bhf);
                        mma_bf16(acc[mi][ni], Ahf[mi], Blf);
                        mma_bf16(acc[mi][ni], Alf[mi], Bhf);
                    }
                }
            }
        }
    }

    // ---- epilogue
    #pragma unroll
    for (int mi = 0; mi < 2; mi++) {
        int row0 = r0 + mwarp + mi * 16 + gq;
        int row1 = row0 + 8;
        float d0 = 0.f, d1 = 0.f;
        if (epi == 1) {
            if (row0 < M) d0 = g_dinv[row0];
            if (row1 < M) d1 = g_dinv[row1];
        }
        #pragma unroll
        for (int ni = 0; ni < 8; ni++) {
            int col = n0 + nwarp + ni * 8 + 2 * tq;
            float* c = acc[mi][ni];
            if (epi == 0) {
                float bx = (col < N) ? bias[col] : 0.f;
                float by = (col + 1 < N) ? bias[col + 1] : 0.f;
                if (row0 < M) {
                    if (col < N)     C[(size_t)row0 * N + col]     = fmaxf(c[0] + bx, 0.f);
                    if (col + 1 < N) C[(size_t)row0 * N + col + 1] = fmaxf(c[1] + by, 0.f);
                }
                if (row1 < M) {
                    if (col < N)     C[(size_t)row1 * N + col]     = fmaxf(c[2] + bx, 0.f);
                    if (col + 1 < N) C[(size_t)row1 * N + col + 1] = fmaxf(c[3] + by, 0.f);
                }
            } else {
                if (row0 < M) {
                    if (col < N)     C[(size_t)row0 * N + col]     = d0 * c[0];
                    if (col + 1 < N) C[(size_t)row0 * N + col + 1] = d0 * c[1];
                }
                if (row1 < M) {
                    if (col < N)     C[(size_t)row1 * N + col]     = d1 * c[2];
                    if (col + 1 < N) C[(size_t)row1 * N + col + 1] = d1 * c[3];
                }
            }
        }
    }
}

// ---------------------------------------------------------------------------
__global__ void group_reduce(const float* __restrict__ out4, int M) {
    __shared__ float s[4 * D4];
    for (int i = threadIdx.x; i < 4 * D4; i += blockDim.x) s[i] = 0.0f;
    __syncthreads();
    int base = blockIdx.x * 256;
    for (int n = 0; n < 256; n++) {
        int node = base + n;
        if (node >= M) break;
        int g = g_group[node];
        const float* row = out4 + (size_t)node * D4;
        for (int c = threadIdx.x; c < D4; c += blockDim.x)
            s[g * D4 + c] += row[c];
    }
    __syncthreads();
    for (int i = threadIdx.x; i < 4 * D4; i += blockDim.x)
        if (s[i] != 0.0f) atomicAdd(&g_gsum[i], s[i]);
}

__global__ void final_out(float* __restrict__ out) {
    int i = blockIdx.x * blockDim.x + threadIdx.x;
    if (i >= 4 * D4) return;
    float c = g_gcnt[i / D4];
    out[i] = (c > 0.0f) ? g_gsum[i] / c : 0.0f;
}

// ---------------------------------------------------------------------------
static inline int ceil_div(long long a, long long b) { return (int)((a + b - 1) / b); }

extern "C" void kernel_launch(void* const* d_in, const int* in_sizes, int n_in,
                              void* d_out, int out_size) {
    const float* x  = (const float*)d_in[0];
    const float* nf = (const float*)d_in[1];
    const int*   ei = (const int*)d_in[2];
    const float* W1 = (const float*)d_in[3];
    const float* b1 = (const float*)d_in[4];
    const float* W2 = (const float*)d_in[5];
    const float* b2 = (const float*)d_in[6];
    const float* W3 = (const float*)d_in[7];
    const float* b3 = (const float*)d_in[8];
    const float* W4 = (const float*)d_in[9];
    const float* b4 = (const float*)d_in[10];
    float* out = (float*)d_out;

    int M = in_sizes[0] / INDIM;     // 50000
    int E = in_sizes[2] / 2;         // 800000

    float *bufA, *bufB, *bufC;
    cudaGetSymbolAddress((void**)&bufA, g_bufA);
    cudaGetSymbolAddress((void**)&bufB, g_bufB);
    cudaGetSymbolAddress((void**)&bufC, g_bufC);

    const int T = 256;
    int gblocks = ceil_div(M, 8);      // gather: 8 warps/block
    int nFill = ceil_div(E, T);
    int nPrep = ceil_div(M, 8);

    // 0..3: CSR build + node metadata
    zero_kernel<<<ceil_div(M, T), T>>>(M);
    count_kernel<<<ceil_div(E, T), T>>>(ei, E);
    scan_kernel<<<1, 1024>>>(M);
    fillprep_kernel<<<nFill + nPrep, T>>>(ei, x, nf, E, M, nFill);

    // 4: Layer-1 gather (dinv folded into source rows)
    gather_kernel<<<gblocks, 256>>>(x, bufB, nullptr, M, INDIM, 0, 1);

    // 5: Layer-1 GEMM (profiled by ncu)
    {
        dim3 g(ceil_div(M, 128), ceil_div(D1, 128));
        gemm_bf16s<<<g, 256>>>(bufB, W1, b1, bufC, M, INDIM, D1, 0);
    }

    // Layer 2
    {
        dim3 g(ceil_div(M, 128), ceil_div(D2, 128));
        gemm_bf16s<<<g, 256>>>(bufC, W2, nullptr, bufA, M, D1, D2, 1);
    }
    gather_kernel<<<gblocks, 256>>>(bufA, bufB, b2, M, D2, 1, 0);

    // Layer 3
    {
        dim3 g(ceil_div(M, 128), ceil_div(D3, 128));
        gemm_bf16s<<<g, 256>>>(bufB, W3, nullptr, bufA, M, D2, D3, 1);
    }
    gather_kernel<<<gblocks, 256>>>(bufA, bufB, b3, M, D3, 2, 0);

    // Layer 4
    gather_kernel<<<gblocks, 256>>>(bufB, bufA, nullptr, M, D3, 0, 0);
    {
        dim3 g(ceil_div(M, 128), ceil_div(D4, 128));
        gemm_bf16s<<<g, 256>>>(bufA, W4, b4, bufC, M, D3, D4, 0);
    }

    // pooling
    group_reduce<<<ceil_div(M, 256), 128>>>(bufC, M);
    final_out<<<ceil_div(4 * D4, T), T>>>(out);
}

// round 7
// speedup vs baseline: 1.4309x; 1.0293x over previous
#include <cuda_runtime.h>
#include <cuda_bf16.h>
#include <cstdint>

#define NMAX    50000
#define EMAX    800000
#define INDIM   100
#define D1      512
#define D2      256
#define D3      128
#define D4      200

// Scratch
__device__ float g_dinv[NMAX];
__device__ int   g_group[NMAX];
__device__ float g_gcnt[4];
__device__ float g_gsum[4 * D4];
__device__ int   g_cnt[NMAX];
__device__ int   g_fill[NMAX];
__device__ int   g_rowptr[NMAX + 1];
__device__ int   g_csr[EMAX];
__device__ float g_bufA[(size_t)NMAX * 256];
__device__ float g_bufB[(size_t)NMAX * 256];
__device__ float g_bufC[(size_t)NMAX * 512];

// ---------------------------------------------------------------------------
__global__ void zero_kernel(int M) {
    int i = blockIdx.x * blockDim.x + threadIdx.x;
    if (i < M) { g_cnt[i] = 0; g_fill[i] = 0; }
    if (i < 4 * D4) g_gsum[i] = 0.0f;
    if (i < 4) g_gcnt[i] = 0.0f;
}

__global__ void count_kernel(const int* __restrict__ ei, int E) {
    int e = blockIdx.x * blockDim.x + threadIdx.x;
    if (e >= E) return;
    atomicAdd(&g_cnt[ei[E + e]], 1);
}

// single-block warp-shuffle scan -> exclusive rowptr
__global__ void scan_kernel(int M) {
    __shared__ int wsum[32];
    __shared__ int carry;
    int t = threadIdx.x, lane = t & 31, w = t >> 5;
    if (t == 0) { carry = 0; g_rowptr[0] = 0; }
    __syncthreads();
    for (int base = 0; base < M; base += 1024) {
        int i = base + t;
        int v = (i < M) ? g_cnt[i] : 0;
        int s = v;
        #pragma unroll
        for (int off = 1; off < 32; off <<= 1) {
            int u = __shfl_up_sync(0xFFFFFFFFu, s, off);
            if (lane >= off) s += u;
        }
        if (lane == 31) wsum[w] = s;
        __syncthreads();
        if (w == 0) {
            int ws = wsum[lane];
            #pragma unroll
            for (int off = 1; off < 32; off <<= 1) {
                int u = __shfl_up_sync(0xFFFFFFFFu, ws, off);
                if (lane >= off) ws += u;
            }
            wsum[lane] = ws;
        }
        __syncthreads();
        int add = (w > 0) ? wsum[w - 1] : 0;
        if (i < M) g_rowptr[i + 1] = carry + add + s;
        int total = wsum[31];
        __syncthreads();
        if (t == 0) carry += total;
        __syncthreads();
    }
}

__global__ void fill_kernel(const int* __restrict__ ei, int E) {
    int e = blockIdx.x * blockDim.x + threadIdx.x;
    if (e >= E) return;
    int d = ei[E + e];
    int pos = atomicAdd(&g_fill[d], 1);
    g_csr[g_rowptr[d] + pos] = ei[e];
}

__global__ void dinv_kernel(int M) {
    int i = blockIdx.x * blockDim.x + threadIdx.x;
    if (i >= M) return;
    g_dinv[i] = rsqrtf((float)(g_rowptr[i + 1] - g_rowptr[i] + 1));
}

// ---------------------------------------------------------------------------
// Gather aggregation: one warp per dst node.
// scale_src: multiply each source row (and self) by dinv[src] while loading.
// classify: compare self row against prototype rows (layer 1, dim=100 only).
// epi 0: out = dinv*acc ; epi 1: relu(dinv*acc+b) ; epi 2: relu(dinv*acc+b)*dinv
__global__ __launch_bounds__(256) void gather_kernel(
    const float* __restrict__ Hs, float* __restrict__ out,
    const float* __restrict__ bias, const float* __restrict__ nf,
    int M, int dim, int epi, int scale_src, int classify)
{
    int warp = (blockIdx.x * blockDim.x + threadIdx.x) >> 5;
    int lane = threadIdx.x & 31;
    if (warp >= M) return;
    int d4 = dim >> 2;
    int c0 = lane, c1 = lane + 32;
    bool p0 = c0 < d4, p1 = c1 < d4;
    int start = g_rowptr[warp], end = g_rowptr[warp + 1];
    float di = g_dinv[warp];

    float4 a0 = make_float4(0.f, 0.f, 0.f, 0.f);
    float4 a1 = make_float4(0.f, 0.f, 0.f, 0.f);
    const float* self = Hs + (size_t)warp * dim;
    float selfs = scale_src ? di : 1.0f;
    if (p0) {
        float4 v = *(const float4*)(self + c0 * 4);
        if (classify) {
            bool e0 = true, e1 = true, e2 = true;
            float4 n0 = *(const float4*)(nf + c0 * 4);
            float4 n1 = *(const float4*)(nf + INDIM + c0 * 4);
            float4 n2 = *(const float4*)(nf + 2 * INDIM + c0 * 4);
            e0 = (v.x == n0.x) && (v.y == n0.y) && (v.z == n0.z) && (v.w == n0.w);
            e1 = (v.x == n1.x) && (v.y == n1.y) && (v.z == n1.z) && (v.w == n1.w);
            e2 = (v.x == n2.x) && (v.y == n2.y) && (v.z == n2.z) && (v.w == n2.w);
            // store votes in a0 temporarily? no — vote directly below via locals
            // (handled after the p0 block through shared warp vote)
            unsigned m = 0xFFFFFFFFu;
            bool A0 = __all_sync(m, e0);
            bool A1 = __all_sync(m, e1);
            bool A2 = __all_sync(m, e2);
            if (lane == 0) {
                int g = A0 ? 0 : (A1 ? 3 : (A2 ? 1 : 2));
                g_group[warp] = g;
                atomicAdd(&g_gcnt[g], 1.0f);
            }
        }
        a0.x = selfs * v.x; a0.y = selfs * v.y; a0.z = selfs * v.z; a0.w = selfs * v.w;
    } else if (classify) {
        // non-participating lanes still join the vote (vacuous true)
        unsigned m = 0xFFFFFFFFu;
        __all_sync(m, true);
        __all_sync(m, true);
        __all_sync(m, true);
    }
    if (p1) {
        float4 v = *(const float4*)(self + c1 * 4);
        a1.x = selfs * v.x; a1.y = selfs * v.y; a1.z = selfs * v.z; a1.w = selfs * v.w;
    }

    int j = start;
    for (; j + 4 <= end; j += 4) {
        int s0 = g_csr[j], s1 = g_csr[j + 1], s2 = g_csr[j + 2], s3 = g_csr[j + 3];
        float d0 = 1.f, d1 = 1.f, d2 = 1.f, d3 = 1.f;
        if (scale_src) { d0 = g_dinv[s0]; d1 = g_dinv[s1]; d2 = g_dinv[s2]; d3 = g_dinv[s3]; }
        const float* r0 = Hs + (size_t)s0 * dim;
        const float* r1 = Hs + (size_t)s1 * dim;
        const float* r2 = Hs + (size_t)s2 * dim;
        const float* r3 = Hs + (size_t)s3 * dim;
        if (p0) {
            float4 v0 = *(const float4*)(r0 + c0 * 4);
            float4 v1 = *(const float4*)(r1 + c0 * 4);
            float4 v2 = *(const float4*)(r2 + c0 * 4);
            float4 v3 = *(const float4*)(r3 + c0 * 4);
            a0.x += d0 * v0.x + d1 * v1.x + d2 * v2.x + d3 * v3.x;
            a0.y += d0 * v0.y + d1 * v1.y + d2 * v2.y + d3 * v3.y;
            a0.z += d0 * v0.z + d1 * v1.z + d2 * v2.z + d3 * v3.z;
            a0.w += d0 * v0.w + d1 * v1.w + d2 * v2.w + d3 * v3.w;
        }
        if (p1) {
            float4 v0 = *(const float4*)(r0 + c1 * 4);
            float4 v1 = *(const float4*)(r1 + c1 * 4);
            float4 v2 = *(const float4*)(r2 + c1 * 4);
            float4 v3 = *(const float4*)(r3 + c1 * 4);
            a1.x += d0 * v0.x + d1 * v1.x + d2 * v2.x + d3 * v3.x;
            a1.y += d0 * v0.y + d1 * v1.y + d2 * v2.y + d3 * v3.y;
            a1.z += d0 * v0.z + d1 * v1.z + d2 * v2.z + d3 * v3.z;
            a1.w += d0 * v0.w + d1 * v1.w + d2 * v2.w + d3 * v3.w;
        }
    }
    for (; j < end; j++) {
        int s = g_csr[j];
        float ds = scale_src ? g_dinv[s] : 1.0f;
        const float* r = Hs + (size_t)s * dim;
        if (p0) {
            float4 v = *(const float4*)(r + c0 * 4);
            a0.x += ds * v.x; a0.y += ds * v.y; a0.z += ds * v.z; a0.w += ds * v.w;
        }
        if (p1) {
            float4 v = *(const float4*)(r + c1 * 4);
            a1.x += ds * v.x; a1.y += ds * v.y; a1.z += ds * v.z; a1.w += ds * v.w;
        }
    }

    float* orow = out + (size_t)warp * dim;
    if (p0) {
        float4 v;
        v.x = di * a0.x; v.y = di * a0.y; v.z = di * a0.z; v.w = di * a0.w;
        if (epi >= 1) {
            float4 b = *(const float4*)(bias + c0 * 4);
            v.x = fmaxf(v.x + b.x, 0.f); v.y = fmaxf(v.y + b.y, 0.f);
            v.z = fmaxf(v.z + b.z, 0.f); v.w = fmaxf(v.w + b.w, 0.f);
            if (epi == 2) { v.x *= di; v.y *= di; v.z *= di; v.w *= di; }
        }
        *(float4*)(orow + c0 * 4) = v;
    }
    if (p1) {
        float4 v;
        v.x = di * a1.x; v.y = di * a1.y; v.z = di * a1.z; v.w = di * a1.w;
        if (epi >= 1) {
            float4 b = *(const float4*)(bias + c1 * 4);
            v.x = fmaxf(v.x + b.x, 0.f); v.y = fmaxf(v.y + b.y, 0.f);
            v.z = fmaxf(v.z + b.z, 0.f); v.w = fmaxf(v.w + b.w, 0.f);
            if (epi == 2) { v.x *= di; v.y *= di; v.z *= di; v.w *= di; }
        }
        *(float4*)(orow + c1 * 4) = v;
    }
}

// ---------------------------------------------------------------------------
// Split-BF16 tensor-core GEMM, ldmatrix + XOR swizzle, K-stage 32.
// Block 128x128, 8 warps, warp tile 32x64, m16n8k16.
// a = ahi + alo; 3-term: ahi*bhi + ahi*blo + alo*bhi.
// epi 0: C = relu(acc + bias) ; epi 1: C = dinv[row] * acc

__device__ __forceinline__ uint32_t pack_bf16(float x, float y) {
    __nv_bfloat16 bx = __float2bfloat16_rn(x);
    __nv_bfloat16 by = __float2bfloat16_rn(y);
    return (uint32_t)__bfloat16_as_ushort(bx) |
           ((uint32_t)__bfloat16_as_ushort(by) << 16);
}

__device__ __forceinline__ void bf16_split(float v, float& hi, float& lo) {
    __nv_bfloat16 h = __float2bfloat16_rn(v);
    hi = __bfloat162float(h);
    lo = v - hi;
}

__device__ __forceinline__ void mma_bf16(float* c, const uint32_t* a, const uint32_t* b) {
    asm volatile(
        "mma.sync.aligned.m16n8k16.row.col.f32.bf16.bf16.f32 "
        "{%0,%1,%2,%3}, {%4,%5,%6,%7}, {%8,%9}, {%0,%1,%2,%3};\n"
        : "+f"(c[0]), "+f"(c[1]), "+f"(c[2]), "+f"(c[3])
        : "r"(a[0]), "r"(a[1]), "r"(a[2]), "r"(a[3]),
          "r"(b[0]), "r"(b[1]));
}

__device__ __forceinline__ void ldsm_x4(uint32_t* r, uint32_t addr) {
    asm volatile("ldmatrix.sync.aligned.m8n8.x4.shared.b16 {%0,%1,%2,%3}, [%4];"
                 : "=r"(r[0]), "=r"(r[1]), "=r"(r[2]), "=r"(r[3]) : "r"(addr));
}
__device__ __forceinline__ void ldsm_x4_t(uint32_t* r, uint32_t addr) {
    asm volatile("ldmatrix.sync.aligned.m8n8.x4.trans.shared.b16 {%0,%1,%2,%3}, [%4];"
                 : "=r"(r[0]), "=r"(r[1]), "=r"(r[2]), "=r"(r[3]) : "r"(addr));
}

__global__ __launch_bounds__(256) void gemm_bf16s(
    const float* __restrict__ A, const float* __restrict__ W,
    const float* __restrict__ bias, float* __restrict__ C,
    int M, int K, int N, int epi)
{
    __shared__ __align__(16) __nv_bfloat16 Ah[128 * 32], Al[128 * 32];
    __shared__ __align__(16) __nv_bfloat16 Bh[32 * 128], Bl[32 * 128];

    int tid = threadIdx.x;
    int r0 = blockIdx.x * 128;
    int n0 = blockIdx.y * 128;
    int wid = tid >> 5, lane = tid & 31;
    int gq = lane >> 2, tq = lane & 3;
    int mwarp = (wid >> 1) * 32;
    int nwarp = (wid & 1) * 64;

    int a_row = tid >> 1, a_h = tid & 1;
    int b_k = tid >> 3, b_g = tid & 7;

    float acc[2][8][4];
    #pragma unroll
    for (int mi = 0; mi < 2; mi++)
        #pragma unroll
        for (int ni = 0; ni < 8; ni++)
            #pragma unroll
            for (int q = 0; q < 4; q++) acc[mi][ni][q] = 0.0f;

    uint32_t Ah_base = (uint32_t)__cvta_generic_to_shared(Ah);
    uint32_t Al_base = (uint32_t)__cvta_generic_to_shared(Al);
    uint32_t Bh_base = (uint32_t)__cvta_generic_to_shared(Bh);
    uint32_t Bl_base = (uint32_t)__cvta_generic_to_shared(Bl);

    int nk = (K + 31) >> 5;
    float aR[16], bR[16];

    auto load_g = [&](int it) {
        int kt = it * 32;
        {
            int gr = r0 + a_row;
            const float* ap = A + (size_t)gr * K;
            #pragma unroll
            for (int q = 0; q < 4; q++) {
                int kg = kt + a_h * 16 + q * 4;
                float4 v = make_float4(0.f, 0.f, 0.f, 0.f);
                if (gr < M && kg < K) v = *(const float4*)(ap + kg);
                aR[q * 4 + 0] = v.x; aR[q * 4 + 1] = v.y;
                aR[q * 4 + 2] = v.z; aR[q * 4 + 3] = v.w;
            }
        }
        {
            int kb = kt + b_k;
            const float* wp = W + (size_t)kb * N;
            #pragma unroll
            for (int q = 0; q < 4; q++) {
                int nb = n0 + b_g * 16 + q * 4;
                float4 v = make_float4(0.f, 0.f, 0.f, 0.f);
                if (kb < K && nb < N) v = *(const float4*)(wp + nb);
                bR[q * 4 + 0] = v.x; bR[q * 4 + 1] = v.y;
                bR[q * 4 + 2] = v.z; bR[q * 4 + 3] = v.w;
            }
        }
    };

    load_g(0);

    for (int it = 0; it < nk; it++) {
        __syncthreads();

        #pragma unroll
        for (int j = 0; j < 2; j++) {
            float h0, l0, h1, l1, h2, l2, h3, l3, h4, l4, h5, l5, h6, l6, h7, l7;
            bf16_split(aR[j*8+0], h0, l0); bf16_split(aR[j*8+1], h1, l1);
            bf16_split(aR[j*8+2], h2, l2); bf16_split(aR[j*8+3], h3, l3);
            bf16_split(aR[j*8+4], h4, l4); bf16_split(aR[j*8+5], h5, l5);
            bf16_split(aR[j*8+6], h6, l6); bf16_split(aR[j*8+7], h7, l7);
            uint4 hv = make_uint4(pack_bf16(h0,h1), pack_bf16(h2,h3),
                                  pack_bf16(h4,h5), pack_bf16(h6,h7));
            uint4 lv = make_uint4(pack_bf16(l0,l1), pack_bf16(l2,l3),
                                  pack_bf16(l4,l5), pack_bf16(l6,l7));
            int unit = a_row * 4 + ((2 * a_h + j) ^ ((a_row >> 1) & 3));
            ((uint4*)Ah)[unit] = hv;
            ((uint4*)Al)[unit] = lv;
        }
        #pragma unroll
        for (int j = 0; j < 2; j++) {
            float h0, l0, h1, l1, h2, l2, h3, l3, h4, l4, h5, l5, h6, l6, h7, l7;
            bf16_split(bR[j*8+0], h0, l0); bf16_split(bR[j*8+1], h1, l1);
            bf16_split(bR[j*8+2], h2, l2); bf16_split(bR[j*8+3], h3, l3);
            bf16_split(bR[j*8+4], h4, l4); bf16_split(bR[j*8+5], h5, l5);
            bf16_split(bR[j*8+6], h6, l6); bf16_split(bR[j*8+7], h7, l7);
            uint4 hv = make_uint4(pack_bf16(h0,h1), pack_bf16(h2,h3),
                                  pack_bf16(h4,h5), pack_bf16(h6,h7));
            uint4 lv = make_uint4(pack_bf16(l0,l1), pack_bf16(l2,l3),
                                  pack_bf16(l4,l5), pack_bf16(l6,l7));
            int unit = b_k * 16 + ((2 * b_g + j) ^ (b_k & 7));
            ((uint4*)Bh)[unit] = hv;
            ((uint4*)Bl)[unit] = lv;
        }
        __syncthreads();

        if (it + 1 < nk) load_g(it + 1);

        #pragma unroll
        for (int ks = 0; ks < 32; ks += 16) {
            uint32_t Ahf[2][4], Alf[2][4];
            #pragma unroll
            for (int mi = 0; mi < 2; mi++) {
                int mrow = mwarp + mi * 16 + (lane & 15);
                int chunk = (ks >> 3) + (lane >> 4);
                int unit = mrow * 4 + (chunk ^ ((mrow >> 1) & 3));
                ldsm_x4(Ahf[mi], Ah_base + unit * 16);
                ldsm_x4(Alf[mi], Al_base + unit * 16);
            }
            #pragma unroll
            for (int p = 0; p < 4; p++) {
                int nbase = nwarp + p * 16;
                int krow = ks + (lane & 7) + ((lane >> 3) & 1) * 8;
                int chunk = (nbase >> 3) + (lane >> 4);
                int unit = krow * 16 + (chunk ^ (krow & 7));
                uint32_t bh[4], bl[4];
                ldsm_x4_t(bh, Bh_base + unit * 16);
                ldsm_x4_t(bl, Bl_base + unit * 16);
                #pragma unroll
                for (int half = 0; half < 2; half++) {
                    int ni = 2 * p + half;
                    uint32_t* Bhf = bh + 2 * half;
                    uint32_t* Blf = bl + 2 * half;
                    #pragma unroll
                    for (int mi = 0; mi < 2; mi++) {
                        mma_bf16(acc[mi][ni], Ahf[mi], Bhf);
                        mma_bf16(acc[mi][ni], Ahf[mi], Blf);
                        mma_bf16(acc[mi][ni], Alf[mi], Bhf);
                    }
                }
            }
        }
    }

    #pragma unroll
    for (int mi = 0; mi < 2; mi++) {
        int row0 = r0 + mwarp + mi * 16 + gq;
        int row1 = row0 + 8;
        float d0 = 0.f, d1 = 0.f;
        if (epi == 1) {
            if (row0 < M) d0 = g_dinv[row0];
            if (row1 < M) d1 = g_dinv[row1];
        }
        #pragma unroll
        for (int ni = 0; ni < 8; ni++) {
            int col = n0 + nwarp + ni * 8 + 2 * tq;
            float* c = acc[mi][ni];
            if (epi == 0) {
                float bx = (col < N) ? bias[col] : 0.f;
                float by = (col + 1 < N) ? bias[col + 1] : 0.f;
                if (row0 < M) {
                    if (col < N)     C[(size_t)row0 * N + col]     = fmaxf(c[0] + bx, 0.f);
                    if (col + 1 < N) C[(size_t)row0 * N + col + 1] = fmaxf(c[1] + by, 0.f);
                }
                if (row1 < M) {
                    if (col < N)     C[(size_t)row1 * N + col]     = fmaxf(c[2] + bx, 0.f);
                    if (col + 1 < N) C[(size_t)row1 * N + col + 1] = fmaxf(c[3] + by, 0.f);
                }
            } else {
                if (row0 < M) {
                    if (col < N)     C[(size_t)row0 * N + col]     = d0 * c[0];
                    if (col + 1 < N) C[(size_t)row0 * N + col + 1] = d0 * c[1];
                }
                if (row1 < M) {
                    if (col < N)     C[(size_t)row1 * N + col]     = d1 * c[2];
                    if (col + 1 < N) C[(size_t)row1 * N + col + 1] = d1 * c[3];
                }
            }
        }
    }
}

// ---------------------------------------------------------------------------
__global__ void group_reduce(const float* __restrict__ out4, int M) {
    __shared__ float s[4 * D4];
    for (int i = threadIdx.x; i < 4 * D4; i += blockDim.x) s[i] = 0.0f;
    __syncthreads();
    int base = blockIdx.x * 256;
    for (int n = 0; n < 256; n++) {
        int node = base + n;
        if (node >= M) break;
        int g = g_group[node];
        const float* row = out4 + (size_t)node * D4;
        for (int c = threadIdx.x; c < D4; c += blockDim.x)
            s[g * D4 + c] += row[c];
    }
    __syncthreads();
    for (int i = threadIdx.x; i < 4 * D4; i += blockDim.x)
        if (s[i] != 0.0f) atomicAdd(&g_gsum[i], s[i]);
}

__global__ void final_out(float* __restrict__ out) {
    int i = blockIdx.x * blockDim.x + threadIdx.x;
    if (i >= 4 * D4) return;
    float c = g_gcnt[i / D4];
    out[i] = (c > 0.0f) ? g_gsum[i] / c : 0.0f;
}

// ---------------------------------------------------------------------------
static inline int ceil_div(long long a, long long b) { return (int)((a + b - 1) / b); }

extern "C" void kernel_launch(void* const* d_in, const int* in_sizes, int n_in,
                              void* d_out, int out_size) {
    const float* x  = (const float*)d_in[0];
    const float* nf = (const float*)d_in[1];
    const int*   ei = (const int*)d_in[2];
    const float* W1 = (const float*)d_in[3];
    const float* b1 = (const float*)d_in[4];
    const float* W2 = (const float*)d_in[5];
    const float* b2 = (const float*)d_in[6];
    const float* W3 = (const float*)d_in[7];
    const float* b3 = (const float*)d_in[8];
    const float* W4 = (const float*)d_in[9];
    const float* b4 = (const float*)d_in[10];
    float* out = (float*)d_out;

    int M = in_sizes[0] / INDIM;     // 50000
    int E = in_sizes[2] / 2;         // 800000

    float *bufA, *bufB, *bufC;
    cudaGetSymbolAddress((void**)&bufA, g_bufA);
    cudaGetSymbolAddress((void**)&bufB, g_bufB);
    cudaGetSymbolAddress((void**)&bufC, g_bufC);

    const int T = 256;
    int gblocks = ceil_div(M, 8);

    // 0..4: CSR build + dinv
    zero_kernel<<<ceil_div(M, T), T>>>(M);
    count_kernel<<<ceil_div(E, T), T>>>(ei, E);
    scan_kernel<<<1, 1024>>>(M);
    fill_kernel<<<ceil_div(E, T), T>>>(ei, E);
    dinv_kernel<<<ceil_div(M, T), T>>>(M);

    // 5: Layer-1 gather (dinv folded; node classification fused) <- ncu slot
    gather_kernel<<<gblocks, 256>>>(x, bufB, nullptr, nf, M, INDIM, 0, 1, 1);

    // Layer-1 GEMM
    {
        dim3 g(ceil_div(M, 128), ceil_div(D1, 128));
        gemm_bf16s<<<g, 256>>>(bufB, W1, b1, bufC, M, INDIM, D1, 0);
    }

    // Layer 2
    {
        dim3 g(ceil_div(M, 128), ceil_div(D2, 128));
        gemm_bf16s<<<g, 256>>>(bufC, W2, nullptr, bufA, M, D1, D2, 1);
    }
    gather_kernel<<<gblocks, 256>>>(bufA, bufB, b2, nullptr, M, D2, 1, 0, 0);

    // Layer 3
    {
        dim3 g(ceil_div(M, 128), ceil_div(D3, 128));
        gemm_bf16s<<<g, 256>>>(bufB, W3, nullptr, bufA, M, D2, D3, 1);
    }
    gather_kernel<<<gblocks, 256>>>(bufA, bufB, b3, nullptr, M, D3, 2, 0, 0);

    // Layer 4
    gather_kernel<<<gblocks, 256>>>(bufB, bufA, nullptr, nullptr, M, D3, 0, 0, 0);
    {
        dim3 g(ceil_div(M, 128), ceil_div(D4, 128));
        gemm_bf16s<<<g, 256>>>(bufA, W4, b4, bufC, M, D3, D4, 0);
    }

    // pooling
    group_reduce<<<ceil_div(M, 256), 128>>>(bufC, M);
    final_out<<<ceil_div(4 * D4, T), T>>>(out);
}

// round 8
// speedup vs baseline: 1.6074x; 1.1233x over previous
#include <cuda_runtime.h>
#include <cuda_bf16.h>
#include <cstdint>

#define NMAX    50000
#define EMAX    800000
#define INDIM   100
#define D1      512
#define D2      256
#define D3      128
#define D4      200

// W segment offsets (elements)
#define WOFF1   0
#define WOFF2   51200
#define WOFF3   182272
#define WOFF4   215040
#define WTOT    240640

// Scratch
__device__ float g_dinv[NMAX];
__device__ int   g_group[NMAX];
__device__ float g_gcnt[4];
__device__ float g_gsum[4 * D4];
__device__ int   g_cnt[NMAX];
__device__ int   g_fill[NMAX];
__device__ int   g_rowptr[NMAX + 1];
__device__ int   g_csr[EMAX];
__device__ __align__(16) __nv_bfloat16 g_Whi[WTOT];
__device__ __align__(16) __nv_bfloat16 g_Wlo[WTOT];
__device__ uint32_t g_bufA[(size_t)NMAX * 256];
__device__ uint32_t g_bufB[(size_t)NMAX * 256];
__device__ uint32_t g_bufC[(size_t)NMAX * 512];   // also used as float for final layer

// ---------------------------------------------------------------------------
// helpers
__device__ __forceinline__ uint32_t packsplit(float v) {
    __nv_bfloat16 h = __float2bfloat16_rn(v);
    float hf = __bfloat162float(h);
    __nv_bfloat16 l = __float2bfloat16_rn(v - hf);
    return (uint32_t)__bfloat16_as_ushort(h) |
           ((uint32_t)__bfloat16_as_ushort(l) << 16);
}
__device__ __forceinline__ float unpk(uint32_t p) {
    float hi = __uint_as_float(p << 16);
    float lo = __uint_as_float(p & 0xFFFF0000u);
    return hi + lo;
}
__device__ __forceinline__ uint32_t prmt(uint32_t a, uint32_t b, uint32_t s) {
    uint32_t r; asm("prmt.b32 %0,%1,%2,%3;" : "=r"(r) : "r"(a), "r"(b), "r"(s));
    return r;
}

// ---------------------------------------------------------------------------
__global__ void zero_kernel(int M) {
    int i = blockIdx.x * blockDim.x + threadIdx.x;
    if (i < M) { g_cnt[i] = 0; g_fill[i] = 0; }
    if (i < 4 * D4) g_gsum[i] = 0.0f;
    if (i < 4) g_gcnt[i] = 0.0f;
}

__global__ void count_kernel(const int* __restrict__ ei, int E) {
    int e = blockIdx.x * blockDim.x + threadIdx.x;
    if (e >= E) return;
    atomicAdd(&g_cnt[ei[E + e]], 1);
}

// single-block warp-shuffle scan -> exclusive rowptr
__global__ void scan_kernel(int M) {
    __shared__ int wsum[32];
    __shared__ int carry;
    int t = threadIdx.x, lane = t & 31, w = t >> 5;
    if (t == 0) { carry = 0; g_rowptr[0] = 0; }
    __syncthreads();
    for (int base = 0; base < M; base += 1024) {
        int i = base + t;
        int v = (i < M) ? g_cnt[i] : 0;
        int s = v;
        #pragma unroll
        for (int off = 1; off < 32; off <<= 1) {
            int u = __shfl_up_sync(0xFFFFFFFFu, s, off);
            if (lane >= off) s += u;
        }
        if (lane == 31) wsum[w] = s;
        __syncthreads();
        if (w == 0) {
            int ws = wsum[lane];
            #pragma unroll
            for (int off = 1; off < 32; off <<= 1) {
                int u = __shfl_up_sync(0xFFFFFFFFu, ws, off);
                if (lane >= off) ws += u;
            }
            wsum[lane] = ws;
        }
        __syncthreads();
        int add = (w > 0) ? wsum[w - 1] : 0;
        if (i < M) g_rowptr[i + 1] = carry + add + s;
        int total = wsum[31];
        __syncthreads();
        if (t == 0) carry += total;
        __syncthreads();
    }
}

__global__ void fill_kernel(const int* __restrict__ ei, int E) {
    int e = blockIdx.x * blockDim.x + threadIdx.x;
    if (e >= E) return;
    int d = ei[E + e];
    int pos = atomicAdd(&g_fill[d], 1);
    g_csr[g_rowptr[d] + pos] = ei[e];
}

// dinv + split all weights to bf16 hi/lo
__global__ void prep_kernel(const float* __restrict__ W1, const float* __restrict__ W2,
                            const float* __restrict__ W3, const float* __restrict__ W4,
                            int M) {
    int i = blockIdx.x * blockDim.x + threadIdx.x;
    if (i < M)
        g_dinv[i] = rsqrtf((float)(g_rowptr[i + 1] - g_rowptr[i] + 1));
    if (i < WTOT) {
        float v;
        if (i < WOFF2)      v = W1[i];
        else if (i < WOFF3) v = W2[i - WOFF2];
        else if (i < WOFF4) v = W3[i - WOFF3];
        else                v = W4[i - WOFF4];
        __nv_bfloat16 h = __float2bfloat16_rn(v);
        g_Whi[i] = h;
        g_Wlo[i] = __float2bfloat16_rn(v - __bfloat162float(h));
    }
}

// ---------------------------------------------------------------------------
// Layer-1 gather: fp32 x input, dim=100 fixed, classification fused,
// sources scaled by dinv[src]; output packed bf16 hi/lo: di * acc.
__global__ __launch_bounds__(256) void gather_x(
    const float* __restrict__ x, uint32_t* __restrict__ out,
    const float* __restrict__ nf, int M)
{
    int warp = (blockIdx.x * blockDim.x + threadIdx.x) >> 5;
    int lane = threadIdx.x & 31;
    if (warp >= M) return;
    const int d4 = INDIM / 4;       // 25
    bool p0 = lane < d4;
    int start = g_rowptr[warp], end = g_rowptr[warp + 1];
    float di = g_dinv[warp];

    float4 a0 = make_float4(0.f, 0.f, 0.f, 0.f);
    bool e0 = true, e1 = true, e2 = true;
    if (p0) {
        float4 v = *(const float4*)(x + (size_t)warp * INDIM + lane * 4);
        float4 n0 = *(const float4*)(nf + lane * 4);
        float4 n1 = *(const float4*)(nf + INDIM + lane * 4);
        float4 n2 = *(const float4*)(nf + 2 * INDIM + lane * 4);
        e0 = (v.x == n0.x) && (v.y == n0.y) && (v.z == n0.z) && (v.w == n0.w);
        e1 = (v.x == n1.x) && (v.y == n1.y) && (v.z == n1.z) && (v.w == n1.w);
        e2 = (v.x == n2.x) && (v.y == n2.y) && (v.z == n2.z) && (v.w == n2.w);
        a0.x = di * v.x; a0.y = di * v.y; a0.z = di * v.z; a0.w = di * v.w;
    }
    unsigned m = 0xFFFFFFFFu;
    bool A0 = __all_sync(m, e0);
    bool A1 = __all_sync(m, e1);
    bool A2 = __all_sync(m, e2);
    if (lane == 0) {
        int g = A0 ? 0 : (A1 ? 3 : (A2 ? 1 : 2));
        g_group[warp] = g;
        atomicAdd(&g_gcnt[g], 1.0f);
    }

    int j = start;
    for (; j + 4 <= end; j += 4) {
        int s0 = g_csr[j], s1 = g_csr[j + 1], s2 = g_csr[j + 2], s3 = g_csr[j + 3];
        float d0 = g_dinv[s0], d1 = g_dinv[s1], d2 = g_dinv[s2], d3 = g_dinv[s3];
        if (p0) {
            float4 v0 = *(const float4*)(x + (size_t)s0 * INDIM + lane * 4);
            float4 v1 = *(const float4*)(x + (size_t)s1 * INDIM + lane * 4);
            float4 v2 = *(const float4*)(x + (size_t)s2 * INDIM + lane * 4);
            float4 v3 = *(const float4*)(x + (size_t)s3 * INDIM + lane * 4);
            a0.x += d0 * v0.x + d1 * v1.x + d2 * v2.x + d3 * v3.x;
            a0.y += d0 * v0.y + d1 * v1.y + d2 * v2.y + d3 * v3.y;
            a0.z += d0 * v0.z + d1 * v1.z + d2 * v2.z + d3 * v3.z;
            a0.w += d0 * v0.w + d1 * v1.w + d2 * v2.w + d3 * v3.w;
        }
    }
    for (; j < end; j++) {
        int s = g_csr[j];
        float ds = g_dinv[s];
        if (p0) {
            float4 v = *(const float4*)(x + (size_t)s * INDIM + lane * 4);
            a0.x += ds * v.x; a0.y += ds * v.y; a0.z += ds * v.z; a0.w += ds * v.w;
        }
    }

    if (p0) {
        uint4 o;
        o.x = packsplit(di * a0.x);
        o.y = packsplit(di * a0.y);
        o.z = packsplit(di * a0.z);
        o.w = packsplit(di * a0.w);
        *(uint4*)(out + (size_t)warp * INDIM + lane * 4) = o;
    }
}

// Packed gather: input/output packed bf16 hi/lo.
// epi 0: out = dinv*acc ; epi 1: relu(dinv*acc+b) ; epi 2: relu(dinv*acc+b)*dinv
__global__ __launch_bounds__(256) void gather_p(
    const uint32_t* __restrict__ Hs, uint32_t* __restrict__ out,
    const float* __restrict__ bias, int M, int dim, int epi)
{
    int warp = (blockIdx.x * blockDim.x + threadIdx.x) >> 5;
    int lane = threadIdx.x & 31;
    if (warp >= M) return;
    int d4 = dim >> 2;
    int c0 = lane, c1 = lane + 32;
    bool p1 = c1 < d4;   // p0 always true for dim>=128
    int start = g_rowptr[warp], end = g_rowptr[warp + 1];
    float di = g_dinv[warp];

    float4 a0, a1 = make_float4(0.f, 0.f, 0.f, 0.f);
    const uint32_t* self = Hs + (size_t)warp * dim;
    {
        uint4 u = *(const uint4*)(self + c0 * 4);
        a0.x = unpk(u.x); a0.y = unpk(u.y); a0.z = unpk(u.z); a0.w = unpk(u.w);
    }
    if (p1) {
        uint4 u = *(const uint4*)(self + c1 * 4);
        a1.x = unpk(u.x); a1.y = unpk(u.y); a1.z = unpk(u.z); a1.w = unpk(u.w);
    }

    int j = start;
    for (; j + 4 <= end; j += 4) {
        int s0 = g_csr[j], s1 = g_csr[j + 1], s2 = g_csr[j + 2], s3 = g_csr[j + 3];
        const uint32_t* r0 = Hs + (size_t)s0 * dim;
        const uint32_t* r1 = Hs + (size_t)s1 * dim;
        const uint32_t* r2 = Hs + (size_t)s2 * dim;
        const uint32_t* r3 = Hs + (size_t)s3 * dim;
        {
            uint4 u0 = *(const uint4*)(r0 + c0 * 4);
            uint4 u1 = *(const uint4*)(r1 + c0 * 4);
            uint4 u2 = *(const uint4*)(r2 + c0 * 4);
            uint4 u3 = *(const uint4*)(r3 + c0 * 4);
            a0.x += unpk(u0.x) + unpk(u1.x) + unpk(u2.x) + unpk(u3.x);
            a0.y += unpk(u0.y) + unpk(u1.y) + unpk(u2.y) + unpk(u3.y);
            a0.z += unpk(u0.z) + unpk(u1.z) + unpk(u2.z) + unpk(u3.z);
            a0.w += unpk(u0.w) + unpk(u1.w) + unpk(u2.w) + unpk(u3.w);
        }
        if (p1) {
            uint4 u0 = *(const uint4*)(r0 + c1 * 4);
            uint4 u1 = *(const uint4*)(r1 + c1 * 4);
            uint4 u2 = *(const uint4*)(r2 + c1 * 4);
            uint4 u3 = *(const uint4*)(r3 + c1 * 4);
            a1.x += unpk(u0.x) + unpk(u1.x) + unpk(u2.x) + unpk(u3.x);
            a1.y += unpk(u0.y) + unpk(u1.y) + unpk(u2.y) + unpk(u3.y);
            a1.z += unpk(u0.z) + unpk(u1.z) + unpk(u2.z) + unpk(u3.z);
            a1.w += unpk(u0.w) + unpk(u1.w) + unpk(u2.w) + unpk(u3.w);
        }
    }
    for (; j < end; j++) {
        int s = g_csr[j];
        const uint32_t* r = Hs + (size_t)s * dim;
        {
            uint4 u = *(const uint4*)(r + c0 * 4);
            a0.x += unpk(u.x); a0.y += unpk(u.y); a0.z += unpk(u.z); a0.w += unpk(u.w);
        }
        if (p1) {
            uint4 u = *(const uint4*)(r + c1 * 4);
            a1.x += unpk(u.x); a1.y += unpk(u.y); a1.z += unpk(u.z); a1.w += unpk(u.w);
        }
    }

    uint32_t* orow = out + (size_t)warp * dim;
    {
        float vx = di * a0.x, vy = di * a0.y, vz = di * a0.z, vw = di * a0.w;
        if (epi >= 1) {
            float4 b = *(const float4*)(bias + c0 * 4);
            vx = fmaxf(vx + b.x, 0.f); vy = fmaxf(vy + b.y, 0.f);
            vz = fmaxf(vz + b.z, 0.f); vw = fmaxf(vw + b.w, 0.f);
            if (epi == 2) { vx *= di; vy *= di; vz *= di; vw *= di; }
        }
        uint4 o = make_uint4(packsplit(vx), packsplit(vy), packsplit(vz), packsplit(vw));
        *(uint4*)(orow + c0 * 4) = o;
    }
    if (p1) {
        float vx = di * a1.x, vy = di * a1.y, vz = di * a1.z, vw = di * a1.w;
        if (epi >= 1) {
            float4 b = *(const float4*)(bias + c1 * 4);
            vx = fmaxf(vx + b.x, 0.f); vy = fmaxf(vy + b.y, 0.f);
            vz = fmaxf(vz + b.z, 0.f); vw = fmaxf(vw + b.w, 0.f);
            if (epi == 2) { vx *= di; vy *= di; vz *= di; vw *= di; }
        }
        uint4 o = make_uint4(packsplit(vx), packsplit(vy), packsplit(vz), packsplit(vw));
        *(uint4*)(orow + c1 * 4) = o;
    }
}

// ---------------------------------------------------------------------------
// Split-BF16 tensor-core GEMM. A packed u32 (hi|lo<<16), W pre-split bf16 planes.
// Block 128x128, 8 warps, warp tile 32x64, m16n8k16, ldmatrix + XOR swizzle.
// epi 0: packed relu(acc+bias) ; epi 1: packed dinv*acc ; epi 2: fp32 relu(acc+bias)

__device__ __forceinline__ void mma_bf16(float* c, const uint32_t* a, const uint32_t* b) {
    asm volatile(
        "mma.sync.aligned.m16n8k16.row.col.f32.bf16.bf16.f32 "
        "{%0,%1,%2,%3}, {%4,%5,%6,%7}, {%8,%9}, {%0,%1,%2,%3};\n"
        : "+f"(c[0]), "+f"(c[1]), "+f"(c[2]), "+f"(c[3])
        : "r"(a[0]), "r"(a[1]), "r"(a[2]), "r"(a[3]),
          "r"(b[0]), "r"(b[1]));
}
__device__ __forceinline__ void ldsm_x4(uint32_t* r, uint32_t addr) {
    asm volatile("ldmatrix.sync.aligned.m8n8.x4.shared.b16 {%0,%1,%2,%3}, [%4];"
                 : "=r"(r[0]), "=r"(r[1]), "=r"(r[2]), "=r"(r[3]) : "r"(addr));
}
__device__ __forceinline__ void ldsm_x4_t(uint32_t* r, uint32_t addr) {
    asm volatile("ldmatrix.sync.aligned.m8n8.x4.trans.shared.b16 {%0,%1,%2,%3}, [%4];"
                 : "=r"(r[0]), "=r"(r[1]), "=r"(r[2]), "=r"(r[3]) : "r"(addr));
}

__global__ __launch_bounds__(256) void gemm_bf16s(
    const uint32_t* __restrict__ A,
    const __nv_bfloat16* __restrict__ Whi, const __nv_bfloat16* __restrict__ Wlo,
    const float* __restrict__ bias, void* __restrict__ Cout,
    int M, int K, int N, int epi)
{
    __shared__ __align__(16) __nv_bfloat16 Ah[128 * 32], Al[128 * 32];
    __shared__ __align__(16) __nv_bfloat16 Bh[32 * 128], Bl[32 * 128];

    int tid = threadIdx.x;
    int r0 = blockIdx.x * 128;
    int n0 = blockIdx.y * 128;
    int wid = tid >> 5, lane = tid & 31;
    int gq = lane >> 2, tq = lane & 3;
    int mwarp = (wid >> 1) * 32;
    int nwarp = (wid & 1) * 64;

    int a_row = tid >> 1, a_h = tid & 1;
    int b_k = tid >> 3, b_g = tid & 7;

    float acc[2][8][4];
    #pragma unroll
    for (int mi = 0; mi < 2; mi++)
        #pragma unroll
        for (int ni = 0; ni < 8; ni++)
            #pragma unroll
            for (int q = 0; q < 4; q++) acc[mi][ni][q] = 0.0f;

    uint32_t Ah_base = (uint32_t)__cvta_generic_to_shared(Ah);
    uint32_t Al_base = (uint32_t)__cvta_generic_to_shared(Al);
    uint32_t Bh_base = (uint32_t)__cvta_generic_to_shared(Bh);
    uint32_t Bl_base = (uint32_t)__cvta_generic_to_shared(Bl);

    int nk = (K + 31) >> 5;
    uint32_t aP[16];
    uint4 bH[2], bL[2];

    auto load_g = [&](int it) {
        int kt = it * 32;
        {
            int gr = r0 + a_row;
            const uint32_t* ap = A + (size_t)gr * K;
            #pragma unroll
            for (int q = 0; q < 4; q++) {
                int kg = kt + a_h * 16 + q * 4;
                uint4 v = make_uint4(0u, 0u, 0u, 0u);
                if (gr < M && kg < K) v = *(const uint4*)(ap + kg);
                aP[q * 4 + 0] = v.x; aP[q * 4 + 1] = v.y;
                aP[q * 4 + 2] = v.z; aP[q * 4 + 3] = v.w;
            }
        }
        {
            int kb = kt + b_k;
            bool rowok = kb < K;
            #pragma unroll
            for (int j = 0; j < 2; j++) {
                int nb = n0 + b_g * 16 + j * 8;
                if (rowok && nb + 7 < N) {
                    bH[j] = *(const uint4*)(Whi + (size_t)kb * N + nb);
                    bL[j] = *(const uint4*)(Wlo + (size_t)kb * N + nb);
                } else {
                    uint32_t wh[4] = {0,0,0,0}, wl[4] = {0,0,0,0};
                    if (rowok) {
                        for (int t = 0; t < 8; t++) {
                            if (nb + t < N) {
                                uint32_t uh = (uint32_t)__bfloat16_as_ushort(Whi[(size_t)kb * N + nb + t]);
                                uint32_t ul = (uint32_t)__bfloat16_as_ushort(Wlo[(size_t)kb * N + nb + t]);
                                wh[t >> 1] |= uh << ((t & 1) * 16);
                                wl[t >> 1] |= ul << ((t & 1) * 16);
                            }
                        }
                    }
                    bH[j] = make_uint4(wh[0], wh[1], wh[2], wh[3]);
                    bL[j] = make_uint4(wl[0], wl[1], wl[2], wl[3]);
                }
            }
        }
    };

    load_g(0);

    for (int it = 0; it < nk; it++) {
        __syncthreads();

        // A: PRMT-separate hi/lo planes, store swizzled chunks
        #pragma unroll
        for (int j = 0; j < 2; j++) {
            const uint32_t* p = aP + j * 8;
            uint4 hv = make_uint4(prmt(p[0], p[1], 0x5410), prmt(p[2], p[3], 0x5410),
                                  prmt(p[4], p[5], 0x5410), prmt(p[6], p[7], 0x5410));
            uint4 lv = make_uint4(prmt(p[0], p[1], 0x7632), prmt(p[2], p[3], 0x7632),
                                  prmt(p[4], p[5], 0x7632), prmt(p[6], p[7], 0x7632));
            int unit = a_row * 4 + ((2 * a_h + j) ^ ((a_row >> 1) & 3));
            ((uint4*)Ah)[unit] = hv;
            ((uint4*)Al)[unit] = lv;
        }
        // B: direct store
        #pragma unroll
        for (int j = 0; j < 2; j++) {
            int unit = b_k * 16 + ((2 * b_g + j) ^ (b_k & 7));
            ((uint4*)Bh)[unit] = bH[j];
            ((uint4*)Bl)[unit] = bL[j];
        }
        __syncthreads();

        if (it + 1 < nk) load_g(it + 1);

        #pragma unroll
        for (int ks = 0; ks < 32; ks += 16) {
            uint32_t Ahf[2][4], Alf[2][4];
            #pragma unroll
            for (int mi = 0; mi < 2; mi++) {
                int mrow = mwarp + mi * 16 + (lane & 15);
                int chunk = (ks >> 3) + (lane >> 4);
                int unit = mrow * 4 + (chunk ^ ((mrow >> 1) & 3));
                ldsm_x4(Ahf[mi], Ah_base + unit * 16);
                ldsm_x4(Alf[mi], Al_base + unit * 16);
            }
            #pragma unroll
            for (int p = 0; p < 4; p++) {
                int nbase = nwarp + p * 16;
                int krow = ks + (lane & 7) + ((lane >> 3) & 1) * 8;
                int chunk = (nbase >> 3) + (lane >> 4);
                int unit = krow * 16 + (chunk ^ (krow & 7));
                uint32_t bh[4], bl[4];
                ldsm_x4_t(bh, Bh_base + unit * 16);
                ldsm_x4_t(bl, Bl_base + unit * 16);
                #pragma unroll
                for (int half = 0; half < 2; half++) {
                    int ni = 2 * p + half;
                    uint32_t* Bhf = bh + 2 * half;
                    uint32_t* Blf = bl + 2 * half;
                    #pragma unroll
                    for (int mi = 0; mi < 2; mi++) {
                        mma_bf16(acc[mi][ni], Ahf[mi], Bhf);
                        mma_bf16(acc[mi][ni], Ahf[mi], Blf);
                        mma_bf16(acc[mi][ni], Alf[mi], Bhf);
                    }
                }
            }
        }
    }

    // epilogue
    uint32_t* Cp = (uint32_t*)Cout;
    float* Cf = (float*)Cout;
    #pragma unroll
    for (int mi = 0; mi < 2; mi++) {
        int row0 = r0 + mwarp + mi * 16 + gq;
        int row1 = row0 + 8;
        float d0 = 0.f, d1 = 0.f;
        if (epi == 1) {
            if (row0 < M) d0 = g_dinv[row0];
            if (row1 < M) d1 = g_dinv[row1];
        }
        #pragma unroll
        for (int ni = 0; ni < 8; ni++) {
            int col = n0 + nwarp + ni * 8 + 2 * tq;
            float* c = acc[mi][ni];
            if (epi == 2) {
                float bx = (col < N) ? bias[col] : 0.f;
                float by = (col + 1 < N) ? bias[col + 1] : 0.f;
                if (row0 < M) {
                    if (col < N)     Cf[(size_t)row0 * N + col]     = fmaxf(c[0] + bx, 0.f);
                    if (col + 1 < N) Cf[(size_t)row0 * N + col + 1] = fmaxf(c[1] + by, 0.f);
                }
                if (row1 < M) {
                    if (col < N)     Cf[(size_t)row1 * N + col]     = fmaxf(c[2] + bx, 0.f);
                    if (col + 1 < N) Cf[(size_t)row1 * N + col + 1] = fmaxf(c[3] + by, 0.f);
                }
            } else if (epi == 0) {
                float bx = (col < N) ? bias[col] : 0.f;
                float by = (col + 1 < N) ? bias[col + 1] : 0.f;
                if (row0 < M) {
                    if (col < N)     Cp[(size_t)row0 * N + col]     = packsplit(fmaxf(c[0] + bx, 0.f));
                    if (col + 1 < N) Cp[(size_t)row0 * N + col + 1] = packsplit(fmaxf(c[1] + by, 0.f));
                }
                if (row1 < M) {
                    if (col < N)     Cp[(size_t)row1 * N + col]     = packsplit(fmaxf(c[2] + bx, 0.f));
                    if (col + 1 < N) Cp[(size_t)row1 * N + col + 1] = packsplit(fmaxf(c[3] + by, 0.f));
                }
            } else {
                if (row0 < M) {
                    if (col < N)     Cp[(size_t)row0 * N + col]     = packsplit(d0 * c[0]);
                    if (col + 1 < N) Cp[(size_t)row0 * N + col + 1] = packsplit(d0 * c[1]);
                }
                if (row1 < M) {
                    if (col < N)     Cp[(size_t)row1 * N + col]     = packsplit(d1 * c[2]);
                    if (col + 1 < N) Cp[(size_t)row1 * N + col + 1] = packsplit(d1 * c[3]);
                }
            }
        }
    }
}

// ---------------------------------------------------------------------------
__global__ void group_reduce(const float* __restrict__ out4, int M) {
    __shared__ float s[4 * D4];
    for (int i = threadIdx.x; i < 4 * D4; i += blockDim.x) s[i] = 0.0f;
    __syncthreads();
    int base = blockIdx.x * 256;
    for (int n = 0; n < 256; n++) {
        int node = base + n;
        if (node >= M) break;
        int g = g_group[node];
        const float* row = out4 + (size_t)node * D4;
        for (int c = threadIdx.x; c < D4; c += blockDim.x)
            s[g * D4 + c] += row[c];
    }
    __syncthreads();
    for (int i = threadIdx.x; i < 4 * D4; i += blockDim.x)
        if (s[i] != 0.0f) atomicAdd(&g_gsum[i], s[i]);
}

__global__ void final_out(float* __restrict__ out) {
    int i = blockIdx.x * blockDim.x + threadIdx.x;
    if (i >= 4 * D4) return;
    float c = g_gcnt[i / D4];
    out[i] = (c > 0.0f) ? g_gsum[i] / c : 0.0f;
}

// ---------------------------------------------------------------------------
static inline int ceil_div(long long a, long long b) { return (int)((a + b - 1) / b); }

extern "C" void kernel_launch(void* const* d_in, const int* in_sizes, int n_in,
                              void* d_out, int out_size) {
    const float* x  = (const float*)d_in[0];
    const float* nf = (const float*)d_in[1];
    const int*   ei = (const int*)d_in[2];
    const float* W1 = (const float*)d_in[3];
    const float* b1 = (const float*)d_in[4];
    const float* W2 = (const float*)d_in[5];
    const float* b2 = (const float*)d_in[6];
    const float* W3 = (const float*)d_in[7];
    const float* b3 = (const float*)d_in[8];
    const float* W4 = (const float*)d_in[9];
    const float* b4 = (const float*)d_in[10];
    float* out = (float*)d_out;

    int M = in_sizes[0] / INDIM;     // 50000
    int E = in_sizes[2] / 2;         // 800000

    uint32_t *bufA, *bufB, *bufC;
    __nv_bfloat16 *whi, *wlo;
    cudaGetSymbolAddress((void**)&bufA, g_bufA);
    cudaGetSymbolAddress((void**)&bufB, g_bufB);
    cudaGetSymbolAddress((void**)&bufC, g_bufC);
    cudaGetSymbolAddress((void**)&whi, g_Whi);
    cudaGetSymbolAddress((void**)&wlo, g_Wlo);

    const int T = 256;
    int gblocks = ceil_div(M, 8);

    // CSR build + dinv + weight split
    zero_kernel<<<ceil_div(M, T), T>>>(M);
    count_kernel<<<ceil_div(E, T), T>>>(ei, E);
    scan_kernel<<<1, 1024>>>(M);
    fill_kernel<<<ceil_div(E, T), T>>>(ei, E);
    prep_kernel<<<ceil_div(WTOT, T), T>>>(W1, W2, W3, W4, M);

    // Layer 1: gather (classify fused) -> GEMM K=100 -> 512, epi0 packed
    gather_x<<<gblocks, 256>>>(x, bufB, nf, M);
    {
        dim3 g(ceil_div(M, 128), ceil_div(D1, 128));
        gemm_bf16s<<<g, 256>>>(bufB, whi + WOFF1, wlo + WOFF1, b1, bufC, M, INDIM, D1, 0);
    }

    // Layer 2: GEMM 512->256 epi1 packed; gather (+b2, relu) packed
    {
        dim3 g(ceil_div(M, 128), ceil_div(D2, 128));
        gemm_bf16s<<<g, 256>>>(bufC, whi + WOFF2, wlo + WOFF2, nullptr, bufA, M, D1, D2, 1);
    }
    gather_p<<<gblocks, 256>>>(bufA, bufB, b2, M, D2, 1);

    // Layer 3: GEMM 256->128 epi1; gather (+b3, relu, *dinv)
    {
        dim3 g(ceil_div(M, 128), ceil_div(D3, 128));
        gemm_bf16s<<<g, 256>>>(bufB, whi + WOFF3, wlo + WOFF3, nullptr, bufA, M, D2, D3, 1);
    }
    gather_p<<<gblocks, 256>>>(bufA, bufB, b3, M, D3, 2);

    // Layer 4: gather agg; GEMM 128->200 epi2 (fp32 + bias + relu)
    gather_p<<<gblocks, 256>>>(bufB, bufA, nullptr, M, D3, 0);
    {
        dim3 g(ceil_div(M, 128), ceil_div(D4, 128));
        gemm_bf16s<<<g, 256>>>(bufA, whi + WOFF4, wlo + WOFF4, b4, bufC, M, D3, D4, 2);
    }

    // pooling
    group_reduce<<<ceil_div(M, 256), 128>>>((const float*)bufC, M);
    final_out<<<ceil_div(4 * D4, T), T>>>(out);
}

// round 9
// speedup vs baseline: 1.8157x; 1.1296x over previous
#include <cuda_runtime.h>
#include <cuda_bf16.h>
#include <cstdint>

#define NMAX    50000
#define EMAX    800000
#define INDIM   100
#define D1      512
#define D2      256
#define D3      128
#define D4      200

// padded (K -> multiple of 32) weight plane offsets, elements
#define W1P     0
#define W2P     65536      // 128*512
#define W3P     196608     // +512*256
#define W4P     229376     // +256*128
#define WTOTP   254976     // +128*200

// Scratch
__device__ float g_dinv[NMAX];
__device__ int   g_group[NMAX];
__device__ float g_gcnt[4];
__device__ float g_gsum[4 * D4];
__device__ int   g_cnt[NMAX];
__device__ int   g_fill[NMAX];
__device__ int   g_rowptr[NMAX + 1];
__device__ int   g_csr[EMAX];
__device__ __align__(16) __nv_bfloat16 g_Whi[WTOTP];
__device__ __align__(16) __nv_bfloat16 g_Wlo[WTOTP];
__device__ uint32_t g_bufA[(size_t)NMAX * 256];
__device__ uint32_t g_bufB[(size_t)NMAX * 256];
__device__ uint32_t g_bufC[(size_t)NMAX * 512];   // also fp32 for final layer

// ---------------------------------------------------------------------------
// helpers
__device__ __forceinline__ uint32_t packsplit(float v) {
    __nv_bfloat16 h = __float2bfloat16_rn(v);
    float hf = __bfloat162float(h);
    __nv_bfloat16 l = __float2bfloat16_rn(v - hf);
    return (uint32_t)__bfloat16_as_ushort(h) |
           ((uint32_t)__bfloat16_as_ushort(l) << 16);
}
__device__ __forceinline__ float unpk(uint32_t p) {
    float hi = __uint_as_float(p << 16);
    float lo = __uint_as_float(p & 0xFFFF0000u);
    return hi + lo;
}
__device__ __forceinline__ uint32_t prmt(uint32_t a, uint32_t b, uint32_t s) {
    uint32_t r; asm("prmt.b32 %0,%1,%2,%3;" : "=r"(r) : "r"(a), "r"(b), "r"(s));
    return r;
}
__device__ __forceinline__ void cp16(uint32_t dst, const void* src, int bytes) {
    asm volatile("cp.async.cg.shared.global [%0], [%1], 16, %2;"
                 :: "r"(dst), "l"(src), "r"(bytes));
}
__device__ __forceinline__ void cp_commit() { asm volatile("cp.async.commit_group;"); }
__device__ __forceinline__ void cp_wait0()  { asm volatile("cp.async.wait_group 0;" ::: "memory"); }

// ---------------------------------------------------------------------------
__global__ void zero_kernel(int M) {
    int i = blockIdx.x * blockDim.x + threadIdx.x;
    if (i < M) { g_cnt[i] = 0; g_fill[i] = 0; }
    if (i < 4 * D4) g_gsum[i] = 0.0f;
    if (i < 4) g_gcnt[i] = 0.0f;
}

__global__ void count_kernel(const int* __restrict__ ei, int E) {
    int e = blockIdx.x * blockDim.x + threadIdx.x;
    if (e >= E) return;
    atomicAdd(&g_cnt[ei[E + e]], 1);
}

// single-block warp-shuffle scan -> exclusive rowptr
__global__ void scan_kernel(int M) {
    __shared__ int wsum[32];
    __shared__ int carry;
    int t = threadIdx.x, lane = t & 31, w = t >> 5;
    if (t == 0) { carry = 0; g_rowptr[0] = 0; }
    __syncthreads();
    for (int base = 0; base < M; base += 1024) {
        int i = base + t;
        int v = (i < M) ? g_cnt[i] : 0;
        int s = v;
        #pragma unroll
        for (int off = 1; off < 32; off <<= 1) {
            int u = __shfl_up_sync(0xFFFFFFFFu, s, off);
            if (lane >= off) s += u;
        }
        if (lane == 31) wsum[w] = s;
        __syncthreads();
        if (w == 0) {
            int ws = wsum[lane];
            #pragma unroll
            for (int off = 1; off < 32; off <<= 1) {
                int u = __shfl_up_sync(0xFFFFFFFFu, ws, off);
                if (lane >= off) ws += u;
            }
            wsum[lane] = ws;
        }
        __syncthreads();
        int add = (w > 0) ? wsum[w - 1] : 0;
        if (i < M) g_rowptr[i + 1] = carry + add + s;
        int total = wsum[31];
        __syncthreads();
        if (t == 0) carry += total;
        __syncthreads();
    }
}

__global__ void fill_kernel(const int* __restrict__ ei, int E) {
    int e = blockIdx.x * blockDim.x + threadIdx.x;
    if (e >= E) return;
    int d = ei[E + e];
    int pos = atomicAdd(&g_fill[d], 1);
    g_csr[g_rowptr[d] + pos] = ei[e];
}

// dinv + split all weights to padded bf16 hi/lo planes (K padded to mult-32)
__global__ void prep_kernel(const float* __restrict__ W1, const float* __restrict__ W2,
                            const float* __restrict__ W3, const float* __restrict__ W4,
                            int M) {
    int i = blockIdx.x * blockDim.x + threadIdx.x;
    if (i < M)
        g_dinv[i] = rsqrtf((float)(g_rowptr[i + 1] - g_rowptr[i] + 1));
    if (i < WTOTP) {
        float v = 0.0f;
        if (i < W2P) {                      // W1 padded: 128 x 512, rows >=100 zero
            int k = i >> 9, n = i & 511;
            if (k < INDIM) v = W1[k * D1 + n];
        } else if (i < W3P) v = W2[i - W2P];
        else if (i < W4P)   v = W3[i - W3P];
        else                v = W4[i - W4P];
        __nv_bfloat16 h = __float2bfloat16_rn(v);
        g_Whi[i] = h;
        g_Wlo[i] = __float2bfloat16_rn(v - __bfloat162float(h));
    }
}

// ---------------------------------------------------------------------------
// Layer-1 gather: fp32 x input, classification fused, sources scaled by dinv[src].
// Output: packed bf16 hi/lo rows, stride 128 (cols 100..127 zero).
__global__ __launch_bounds__(256) void gather_x(
    const float* __restrict__ x, uint32_t* __restrict__ out,
    const float* __restrict__ nf, int M)
{
    int warp = (blockIdx.x * blockDim.x + threadIdx.x) >> 5;
    int lane = threadIdx.x & 31;
    if (warp >= M) return;
    const int d4 = INDIM / 4;       // 25
    bool p0 = lane < d4;
    int start = g_rowptr[warp], end = g_rowptr[warp + 1];
    float di = g_dinv[warp];

    float4 a0 = make_float4(0.f, 0.f, 0.f, 0.f);
    bool e0 = true, e1 = true, e2 = true;
    if (p0) {
        float4 v = *(const float4*)(x + (size_t)warp * INDIM + lane * 4);
        float4 n0 = *(const float4*)(nf + lane * 4);
        float4 n1 = *(const float4*)(nf + INDIM + lane * 4);
        float4 n2 = *(const float4*)(nf + 2 * INDIM + lane * 4);
        e0 = (v.x == n0.x) && (v.y == n0.y) && (v.z == n0.z) && (v.w == n0.w);
        e1 = (v.x == n1.x) && (v.y == n1.y) && (v.z == n1.z) && (v.w == n1.w);
        e2 = (v.x == n2.x) && (v.y == n2.y) && (v.z == n2.z) && (v.w == n2.w);
        a0.x = di * v.x; a0.y = di * v.y; a0.z = di * v.z; a0.w = di * v.w;
    }
    unsigned m = 0xFFFFFFFFu;
    bool A0 = __all_sync(m, e0);
    bool A1 = __all_sync(m, e1);
    bool A2 = __all_sync(m, e2);
    if (lane == 0) {
        int g = A0 ? 0 : (A1 ? 3 : (A2 ? 1 : 2));
        g_group[warp] = g;
        atomicAdd(&g_gcnt[g], 1.0f);
    }

    int j = start;
    for (; j + 4 <= end; j += 4) {
        int s0 = g_csr[j], s1 = g_csr[j + 1], s2 = g_csr[j + 2], s3 = g_csr[j + 3];
        float d0 = g_dinv[s0], d1 = g_dinv[s1], d2 = g_dinv[s2], d3 = g_dinv[s3];
        if (p0) {
            float4 v0 = *(const float4*)(x + (size_t)s0 * INDIM + lane * 4);
            float4 v1 = *(const float4*)(x + (size_t)s1 * INDIM + lane * 4);
            float4 v2 = *(const float4*)(x + (size_t)s2 * INDIM + lane * 4);
            float4 v3 = *(const float4*)(x + (size_t)s3 * INDIM + lane * 4);
            a0.x += d0 * v0.x + d1 * v1.x + d2 * v2.x + d3 * v3.x;
            a0.y += d0 * v0.y + d1 * v1.y + d2 * v2.y + d3 * v3.y;
            a0.z += d0 * v0.z + d1 * v1.z + d2 * v2.z + d3 * v3.z;
            a0.w += d0 * v0.w + d1 * v1.w + d2 * v2.w + d3 * v3.w;
        }
    }
    for (; j < end; j++) {
        int s = g_csr[j];
        float ds = g_dinv[s];
        if (p0) {
            float4 v = *(const float4*)(x + (size_t)s * INDIM + lane * 4);
            a0.x += ds * v.x; a0.y += ds * v.y; a0.z += ds * v.z; a0.w += ds * v.w;
        }
    }

    uint4 o = make_uint4(0u, 0u, 0u, 0u);
    if (p0) {
        o.x = packsplit(di * a0.x);
        o.y = packsplit(di * a0.y);
        o.z = packsplit(di * a0.z);
        o.w = packsplit(di * a0.w);
    }
    *(uint4*)(out + (size_t)warp * 128 + lane * 4) = o;
}

// Packed gather: input/output packed bf16 hi/lo.
// epi 0: out = dinv*acc ; epi 1: relu(dinv*acc+b) ; epi 2: relu(dinv*acc+b)*dinv
__global__ __launch_bounds__(256) void gather_p(
    const uint32_t* __restrict__ Hs, uint32_t* __restrict__ out,
    const float* __restrict__ bias, int M, int dim, int epi)
{
    int warp = (blockIdx.x * blockDim.x + threadIdx.x) >> 5;
    int lane = threadIdx.x & 31;
    if (warp >= M) return;
    int d4 = dim >> 2;
    int c0 = lane, c1 = lane + 32;
    bool p1 = c1 < d4;
    int start = g_rowptr[warp], end = g_rowptr[warp + 1];
    float di = g_dinv[warp];

    float4 a0, a1 = make_float4(0.f, 0.f, 0.f, 0.f);
    const uint32_t* self = Hs + (size_t)warp * dim;
    {
        uint4 u = *(const uint4*)(self + c0 * 4);
        a0.x = unpk(u.x); a0.y = unpk(u.y); a0.z = unpk(u.z); a0.w = unpk(u.w);
    }
    if (p1) {
        uint4 u = *(const uint4*)(self + c1 * 4);
        a1.x = unpk(u.x); a1.y = unpk(u.y); a1.z = unpk(u.z); a1.w = unpk(u.w);
    }

    int j = start;
    for (; j + 4 <= end; j += 4) {
        int s0 = g_csr[j], s1 = g_csr[j + 1], s2 = g_csr[j + 2], s3 = g_csr[j + 3];
        const uint32_t* r0 = Hs + (size_t)s0 * dim;
        const uint32_t* r1 = Hs + (size_t)s1 * dim;
        const uint32_t* r2 = Hs + (size_t)s2 * dim;
        const uint32_t* r3 = Hs + (size_t)s3 * dim;
        {
            uint4 u0 = *(const uint4*)(r0 + c0 * 4);
            uint4 u1 = *(const uint4*)(r1 + c0 * 4);
            uint4 u2 = *(const uint4*)(r2 + c0 * 4);
            uint4 u3 = *(const uint4*)(r3 + c0 * 4);
            a0.x += unpk(u0.x) + unpk(u1.x) + unpk(u2.x) + unpk(u3.x);
            a0.y += unpk(u0.y) + unpk(u1.y) + unpk(u2.y) + unpk(u3.y);
            a0.z += unpk(u0.z) + unpk(u1.z) + unpk(u2.z) + unpk(u3.z);
            a0.w += unpk(u0.w) + unpk(u1.w) + unpk(u2.w) + unpk(u3.w);
        }
        if (p1) {
            uint4 u0 = *(const uint4*)(r0 + c1 * 4);
            uint4 u1 = *(const uint4*)(r1 + c1 * 4);
            uint4 u2 = *(const uint4*)(r2 + c1 * 4);
            uint4 u3 = *(const uint4*)(r3 + c1 * 4);
            a1.x += unpk(u0.x) + unpk(u1.x) + unpk(u2.x) + unpk(u3.x);
            a1.y += unpk(u0.y) + unpk(u1.y) + unpk(u2.y) + unpk(u3.y);
            a1.z += unpk(u0.z) + unpk(u1.z) + unpk(u2.z) + unpk(u3.z);
            a1.w += unpk(u0.w) + unpk(u1.w) + unpk(u2.w) + unpk(u3.w);
        }
    }
    for (; j < end; j++) {
        int s = g_csr[j];
        const uint32_t* r = Hs + (size_t)s * dim;
        {
            uint4 u = *(const uint4*)(r + c0 * 4);
            a0.x += unpk(u.x); a0.y += unpk(u.y); a0.z += unpk(u.z); a0.w += unpk(u.w);
        }
        if (p1) {
            uint4 u = *(const uint4*)(r + c1 * 4);
            a1.x += unpk(u.x); a1.y += unpk(u.y); a1.z += unpk(u.z); a1.w += unpk(u.w);
        }
    }

    uint32_t* orow = out + (size_t)warp * dim;
    {
        float vx = di * a0.x, vy = di * a0.y, vz = di * a0.z, vw = di * a0.w;
        if (epi >= 1) {
            float4 b = *(const float4*)(bias + c0 * 4);
            vx = fmaxf(vx + b.x, 0.f); vy = fmaxf(vy + b.y, 0.f);
            vz = fmaxf(vz + b.z, 0.f); vw = fmaxf(vw + b.w, 0.f);
            if (epi == 2) { vx *= di; vy *= di; vz *= di; vw *= di; }
        }
        uint4 o = make_uint4(packsplit(vx), packsplit(vy), packsplit(vz), packsplit(vw));
        *(uint4*)(orow + c0 * 4) = o;
    }
    if (p1) {
        float vx = di * a1.x, vy = di * a1.y, vz = di * a1.z, vw = di * a1.w;
        if (epi >= 1) {
            float4 b = *(const float4*)(bias + c1 * 4);
            vx = fmaxf(vx + b.x, 0.f); vy = fmaxf(vy + b.y, 0.f);
            vz = fmaxf(vz + b.z, 0.f); vw = fmaxf(vw + b.w, 0.f);
            if (epi == 2) { vx *= di; vy *= di; vz *= di; vw *= di; }
        }
        uint4 o = make_uint4(packsplit(vx), packsplit(vy), packsplit(vz), packsplit(vw));
        *(uint4*)(orow + c1 * 4) = o;
    }
}

// ---------------------------------------------------------------------------
// Split-BF16 TC GEMM. A packed u32, W pre-split padded planes (K mult-32).
// Double-buffered smem (64KB dynamic), cp.async for B, ldmatrix + XOR swizzle.
// Block 128x128, 8 warps, warp tile 32x64, m16n8k16, 3-term compensation.
// epi 0: packed relu(acc+bias) ; epi 1: packed dinv*acc ; epi 2: fp32 relu(acc+bias)

__device__ __forceinline__ void mma_bf16(float* c, const uint32_t* a, const uint32_t* b) {
    asm volatile(
        "mma.sync.aligned.m16n8k16.row.col.f32.bf16.bf16.f32 "
        "{%0,%1,%2,%3}, {%4,%5,%6,%7}, {%8,%9}, {%0,%1,%2,%3};\n"
        : "+f"(c[0]), "+f"(c[1]), "+f"(c[2]), "+f"(c[3])
        : "r"(a[0]), "r"(a[1]), "r"(a[2]), "r"(a[3]),
          "r"(b[0]), "r"(b[1]));
}
__device__ __forceinline__ void ldsm_x4(uint32_t* r, uint32_t addr) {
    asm volatile("ldmatrix.sync.aligned.m8n8.x4.shared.b16 {%0,%1,%2,%3}, [%4];"
                 : "=r"(r[0]), "=r"(r[1]), "=r"(r[2]), "=r"(r[3]) : "r"(addr));
}
__device__ __forceinline__ void ldsm_x4_t(uint32_t* r, uint32_t addr) {
    asm volatile("ldmatrix.sync.aligned.m8n8.x4.trans.shared.b16 {%0,%1,%2,%3}, [%4];"
                 : "=r"(r[0]), "=r"(r[1]), "=r"(r[2]), "=r"(r[3]) : "r"(addr));
}

#define GEMM_SMEM 65536

__global__ __launch_bounds__(256, 2) void gemm_bf16s(
    const uint32_t* __restrict__ A,
    const __nv_bfloat16* __restrict__ Whi, const __nv_bfloat16* __restrict__ Wlo,
    const float* __restrict__ bias, void* __restrict__ Cout,
    int M, int K, int N, int epi)
{
    extern __shared__ __align__(16) char smem[];
    // layout (bytes): Ah[2][8192] @0, Al[2][8192] @16384, Bh[2][8192] @32768, Bl[2][8192] @49152
    uint32_t sbase = (uint32_t)__cvta_generic_to_shared(smem);

    int tid = threadIdx.x;
    int r0 = blockIdx.x * 128;
    int n0 = blockIdx.y * 128;
    int wid = tid >> 5, lane = tid & 31;
    int gq = lane >> 2, tq = lane & 3;
    int mwarp = (wid >> 1) * 32;
    int nwarp = (wid & 1) * 64;

    int a_row = tid >> 1, a_h = tid & 1;
    int b_k = tid >> 3, b_g = tid & 7;

    float acc[2][8][4];
    #pragma unroll
    for (int mi = 0; mi < 2; mi++)
        #pragma unroll
        for (int ni = 0; ni < 8; ni++)
            #pragma unroll
            for (int q = 0; q < 4; q++) acc[mi][ni][q] = 0.0f;

    int nk = K >> 5;                 // K is a multiple of 32
    uint32_t aP[16];
    bool arow_ok = (r0 + a_row) < M;
    const uint32_t* aptr = A + (size_t)(r0 + a_row) * K + a_h * 16;

    // B cp.async: 2 chunks x 2 planes per thread per stage
    int nb0 = n0 + b_g * 16;
    int bytes0 = (nb0 < N) ? 16 : 0;
    int bytes1 = (nb0 + 8 < N) ? 16 : 0;
    int nbc0 = (nb0 < N) ? nb0 : 0;
    int nbc1 = (nb0 + 8 < N) ? nb0 + 8 : 0;
    int unitB0 = b_k * 16 + ((2 * b_g) ^ (b_k & 7));
    int unitB1 = b_k * 16 + ((2 * b_g + 1) ^ (b_k & 7));

    auto issue_b = [&](int it, int s) {
        int kb = it * 32 + b_k;
        const __nv_bfloat16* sh = Whi + (size_t)kb * N;
        const __nv_bfloat16* sl = Wlo + (size_t)kb * N;
        uint32_t bh = sbase + 32768 + s * 8192;
        uint32_t bl = sbase + 49152 + s * 8192;
        cp16(bh + unitB0 * 16, sh + nbc0, bytes0);
        cp16(bh + unitB1 * 16, sh + nbc1, bytes1);
        cp16(bl + unitB0 * 16, sl + nbc0, bytes0);
        cp16(bl + unitB1 * 16, sl + nbc1, bytes1);
        cp_commit();
    };
    auto load_a = [&](int it) {
        const uint32_t* p = aptr + it * 32;
        #pragma unroll
        for (int q = 0; q < 4; q++) {
            uint4 v = make_uint4(0u, 0u, 0u, 0u);
            if (arow_ok) v = *(const uint4*)(p + q * 4);
            aP[q * 4 + 0] = v.x; aP[q * 4 + 1] = v.y;
            aP[q * 4 + 2] = v.z; aP[q * 4 + 3] = v.w;
        }
    };
    auto store_a = [&](int s) {
        char* ah = smem + s * 8192;
        char* al = smem + 16384 + s * 8192;
        #pragma unroll
        for (int j = 0; j < 2; j++) {
            const uint32_t* p = aP + j * 8;
            uint4 hv = make_uint4(prmt(p[0], p[1], 0x5410), prmt(p[2], p[3], 0x5410),
                                  prmt(p[4], p[5], 0x5410), prmt(p[6], p[7], 0x5410));
            uint4 lv = make_uint4(prmt(p[0], p[1], 0x7632), prmt(p[2], p[3], 0x7632),
                                  prmt(p[4], p[5], 0x7632), prmt(p[6], p[7], 0x7632));
            int unit = a_row * 4 + ((2 * a_h + j) ^ ((a_row >> 1) & 3));
            ((uint4*)ah)[unit] = hv;
            ((uint4*)al)[unit] = lv;
        }
    };
    auto compute = [&](int s) {
        uint32_t AhS = sbase + s * 8192;
        uint32_t AlS = sbase + 16384 + s * 8192;
        uint32_t BhS = sbase + 32768 + s * 8192;
        uint32_t BlS = sbase + 49152 + s * 8192;
        #pragma unroll
        for (int ks = 0; ks < 32; ks += 16) {
            uint32_t Ahf[2][4], Alf[2][4];
            #pragma unroll
            for (int mi = 0; mi < 2; mi++) {
                int mrow = mwarp + mi * 16 + (lane & 15);
                int chunk = (ks >> 3) + (lane >> 4);
                int unit = mrow * 4 + (chunk ^ ((mrow >> 1) & 3));
                ldsm_x4(Ahf[mi], AhS + unit * 16);
                ldsm_x4(Alf[mi], AlS + unit * 16);
            }
            #pragma unroll
            for (int p = 0; p < 4; p++) {
                int nbase = nwarp + p * 16;
                int krow = ks + (lane & 7) + ((lane >> 3) & 1) * 8;
                int chunk = (nbase >> 3) + (lane >> 4);
                int unit = krow * 16 + (chunk ^ (krow & 7));
                uint32_t bh[4], bl[4];
                ldsm_x4_t(bh, BhS + unit * 16);
                ldsm_x4_t(bl, BlS + unit * 16);
                #pragma unroll
                for (int half = 0; half < 2; half++) {
                    int ni = 2 * p + half;
                    uint32_t* Bhf = bh + 2 * half;
                    uint32_t* Blf = bl + 2 * half;
                    #pragma unroll
                    for (int mi = 0; mi < 2; mi++) {
                        mma_bf16(acc[mi][ni], Ahf[mi], Bhf);
                        mma_bf16(acc[mi][ni], Ahf[mi], Blf);
                        mma_bf16(acc[mi][ni], Alf[mi], Bhf);
                    }
                }
            }
        }
    };

    // prologue: fill stage 0
    issue_b(0, 0);
    load_a(0);
    store_a(0);
    cp_wait0();
    __syncthreads();

    int st = 0;
    for (int it = 0; it < nk; it++) {
        bool more = (it + 1 < nk);
        if (more) {
            issue_b(it + 1, st ^ 1);
            load_a(it + 1);
        }
        compute(st);
        if (more) {
            store_a(st ^ 1);
            cp_wait0();
            __syncthreads();
            st ^= 1;
        }
    }

    // epilogue
    uint32_t* Cp = (uint32_t*)Cout;
    float* Cf = (float*)Cout;
    #pragma unroll
    for (int mi = 0; mi < 2; mi++) {
        int row0 = r0 + mwarp + mi * 16 + gq;
        int row1 = row0 + 8;
        float d0 = 0.f, d1 = 0.f;
        if (epi == 1) {
            if (row0 < M) d0 = g_dinv[row0];
            if (row1 < M) d1 = g_dinv[row1];
        }
        #pragma unroll
        for (int ni = 0; ni < 8; ni++) {
            int col = n0 + nwarp + ni * 8 + 2 * tq;
            float* c = acc[mi][ni];
            if (epi == 2) {
                float bx = (col < N) ? bias[col] : 0.f;
                float by = (col + 1 < N) ? bias[col + 1] : 0.f;
                if (row0 < M) {
                    if (col < N)     Cf[(size_t)row0 * N + col]     = fmaxf(c[0] + bx, 0.f);
                    if (col + 1 < N) Cf[(size_t)row0 * N + col + 1] = fmaxf(c[1] + by, 0.f);
                }
                if (row1 < M) {
                    if (col < N)     Cf[(size_t)row1 * N + col]     = fmaxf(c[2] + bx, 0.f);
                    if (col + 1 < N) Cf[(size_t)row1 * N + col + 1] = fmaxf(c[3] + by, 0.f);
                }
            } else if (epi == 0) {
                float bx = (col < N) ? bias[col] : 0.f;
                float by = (col + 1 < N) ? bias[col + 1] : 0.f;
                if (row0 < M) {
                    if (col < N)     Cp[(size_t)row0 * N + col]     = packsplit(fmaxf(c[0] + bx, 0.f));
                    if (col + 1 < N) Cp[(size_t)row0 * N + col + 1] = packsplit(fmaxf(c[1] + by, 0.f));
                }
                if (row1 < M) {
                    if (col < N)     Cp[(size_t)row1 * N + col]     = packsplit(fmaxf(c[2] + bx, 0.f));
                    if (col + 1 < N) Cp[(size_t)row1 * N + col + 1] = packsplit(fmaxf(c[3] + by, 0.f));
                }
            } else {
                if (row0 < M) {
                    if (col < N)     Cp[(size_t)row0 * N + col]     = packsplit(d0 * c[0]);
                    if (col + 1 < N) Cp[(size_t)row0 * N + col + 1] = packsplit(d0 * c[1]);
                }
                if (row1 < M) {
                    if (col < N)     Cp[(size_t)row1 * N + col]     = packsplit(d1 * c[2]);
                    if (col + 1 < N) Cp[(size_t)row1 * N + col + 1] = packsplit(d1 * c[3]);
                }
            }
        }
    }
}

// ---------------------------------------------------------------------------
__global__ void group_reduce(const float* __restrict__ out4, int M) {
    __shared__ float s[4 * D4];
    for (int i = threadIdx.x; i < 4 * D4; i += blockDim.x) s[i] = 0.0f;
    __syncthreads();
    int base = blockIdx.x * 256;
    for (int n = 0; n < 256; n++) {
        int node = base + n;
        if (node >= M) break;
        int g = g_group[node];
        const float* row = out4 + (size_t)node * D4;
        for (int c = threadIdx.x; c < D4; c += blockDim.x)
            s[g * D4 + c] += row[c];
    }
    __syncthreads();
    for (int i = threadIdx.x; i < 4 * D4; i += blockDim.x)
        if (s[i] != 0.0f) atomicAdd(&g_gsum[i], s[i]);
}

__global__ void final_out(float* __restrict__ out) {
    int i = blockIdx.x * blockDim.x + threadIdx.x;
    if (i >= 4 * D4) return;
    float c = g_gcnt[i / D4];
    out[i] = (c > 0.0f) ? g_gsum[i] / c : 0.0f;
}

// ---------------------------------------------------------------------------
static inline int ceil_div(long long a, long long b) { return (int)((a + b - 1) / b); }

extern "C" void kernel_launch(void* const* d_in, const int* in_sizes, int n_in,
                              void* d_out, int out_size) {
    const float* x  = (const float*)d_in[0];
    const float* nf = (const float*)d_in[1];
    const int*   ei = (const int*)d_in[2];
    const float* W1 = (const float*)d_in[3];
    const float* b1 = (const float*)d_in[4];
    const float* W2 = (const float*)d_in[5];
    const float* b2 = (const float*)d_in[6];
    const float* W3 = (const float*)d_in[7];
    const float* b3 = (const float*)d_in[8];
    const float* W4 = (const float*)d_in[9];
    const float* b4 = (const float*)d_in[10];
    float* out = (float*)d_out;

    int M = in_sizes[0] / INDIM;     // 50000
    int E = in_sizes[2] / 2;         // 800000

    uint32_t *bufA, *bufB, *bufC;
    __nv_bfloat16 *whi, *wlo;
    cudaGetSymbolAddress((void**)&bufA, g_bufA);
    cudaGetSymbolAddress((void**)&bufB, g_bufB);
    cudaGetSymbolAddress((void**)&bufC, g_bufC);
    cudaGetSymbolAddress((void**)&whi, g_Whi);
    cudaGetSymbolAddress((void**)&wlo, g_Wlo);

    static int smem_set = 0;
    if (!smem_set) {
        cudaFuncSetAttribute(gemm_bf16s, cudaFuncAttributeMaxDynamicSharedMemorySize, GEMM_SMEM);
        smem_set = 1;
    }

    const int T = 256;
    int gblocks = ceil_div(M, 8);

    // CSR build + dinv + weight split
    zero_kernel<<<ceil_div(M, T), T>>>(M);
    count_kernel<<<ceil_div(E, T), T>>>(ei, E);
    scan_kernel<<<1, 1024>>>(M);
    fill_kernel<<<ceil_div(E, T), T>>>(ei, E);
    prep_kernel<<<ceil_div(WTOTP, T), T>>>(W1, W2, W3, W4, M);

    // Layer 1: gather (classify fused, pad to K=128) -> GEMM 128->512 epi0
    gather_x<<<gblocks, 256>>>(x, bufB, nf, M);
    {
        dim3 g(ceil_div(M, 128), ceil_div(D1, 128));
        gemm_bf16s<<<g, 256, GEMM_SMEM>>>(bufB, whi + W1P, wlo + W1P, b1, bufC, M, 128, D1, 0);
    }

    // Layer 2: GEMM 512->256 epi1; gather (+b2, relu)
    {
        dim3 g(ceil_div(M, 128), ceil_div(D2, 128));
        gemm_bf16s<<<g, 256, GEMM_SMEM>>>(bufC, whi + W2P, wlo + W2P, nullptr, bufA, M, D1, D2, 1);
    }
    gather_p<<<gblocks, 256>>>(bufA, bufB, b2, M, D2, 1);

    // Layer 3: GEMM 256->128 epi1; gather (+b3, relu, *dinv)
    {
        dim3 g(ceil_div(M, 128), ceil_div(D3, 128));
        gemm_bf16s<<<g, 256, GEMM_SMEM>>>(bufB, whi + W3P, wlo + W3P, nullptr, bufA, M, D2, D3, 1);
    }
    gather_p<<<gblocks, 256>>>(bufA, bufB, b3, M, D3, 2);

    // Layer 4: gather agg; GEMM 128->200 epi2 (fp32 + bias + relu)
    gather_p<<<gblocks, 256>>>(bufB, bufA, nullptr, M, D3, 0);
    {
        dim3 g(ceil_div(M, 128), ceil_div(D4, 128));
        gemm_bf16s<<<g, 256, GEMM_SMEM>>>(bufA, whi + W4P, wlo + W4P, b4, bufC, M, D3, D4, 2);
    }

    // pooling
    group_reduce<<<ceil_div(M, 256), 128>>>((const float*)bufC, M);
    final_out<<<ceil_div(4 * D4, T), T>>>(out);
}

// round 10
// speedup vs baseline: 1.8751x; 1.0328x over previous
#include <cuda_runtime.h>
#include <cuda_bf16.h>
#include <cstdint>

#define NMAX    50000
#define EMAX    800000
#define INDIM   100
#define D1      512
#define D2      256
#define D3      128
#define D4      200

// padded (K -> multiple of 32) weight plane offsets, elements
#define W1P     0
#define W2P     65536      // 128*512
#define W3P     196608     // +512*256
#define W4P     229376     // +256*128
#define WTOTP   254976     // +128*200

// Scratch
__device__ float g_dinv[NMAX];
__device__ int   g_group[NMAX];
__device__ float g_gcnt[4];
__device__ float g_gsum[4 * D4];
__device__ int   g_cnt[NMAX];
__device__ int   g_fill[NMAX];
__device__ int   g_rowptr[NMAX + 1];
__device__ int   g_csr[EMAX];
__device__ __align__(16) __nv_bfloat16 g_Whi[WTOTP];
__device__ __align__(16) __nv_bfloat16 g_Wlo[WTOTP];
// activation planes (hi/lo bf16)
__device__ __align__(16) __nv_bfloat16 g_Ahi[(size_t)NMAX * 256];
__device__ __align__(16) __nv_bfloat16 g_Alo[(size_t)NMAX * 256];
__device__ __align__(16) __nv_bfloat16 g_Bhi[(size_t)NMAX * 256];
__device__ __align__(16) __nv_bfloat16 g_Blo[(size_t)NMAX * 256];
__device__ __align__(16) __nv_bfloat16 g_Chi[(size_t)NMAX * 512];
__device__ __align__(16) __nv_bfloat16 g_Clo[(size_t)NMAX * 512];
__device__ __align__(16) float g_fout[(size_t)NMAX * D4];

// ---------------------------------------------------------------------------
// helpers
__device__ __forceinline__ uint32_t packb2(float x, float y) {
    // result: lower16 = bf16(x), upper16 = bf16(y)
    uint32_t r;
    asm("cvt.rn.bf16x2.f32 %0, %1, %2;" : "=r"(r) : "f"(y), "f"(x));
    return r;
}
__device__ __forceinline__ float blo(uint32_t u) { return __uint_as_float(u << 16); }
__device__ __forceinline__ float bhi(uint32_t u) { return __uint_as_float(u & 0xFFFF0000u); }

__device__ __forceinline__ void cp16(uint32_t dst, const void* src, int bytes) {
    asm volatile("cp.async.cg.shared.global [%0], [%1], 16, %2;"
                 :: "r"(dst), "l"(src), "r"(bytes));
}
__device__ __forceinline__ void cp_commit() { asm volatile("cp.async.commit_group;"); }
__device__ __forceinline__ void cp_wait0()  { asm volatile("cp.async.wait_group 0;" ::: "memory"); }

// ---------------------------------------------------------------------------
__global__ void zero_kernel(int M) {
    int i = blockIdx.x * blockDim.x + threadIdx.x;
    if (i < M) { g_cnt[i] = 0; g_fill[i] = 0; }
    if (i < 4 * D4) g_gsum[i] = 0.0f;
    if (i < 4) g_gcnt[i] = 0.0f;
}

__global__ void count_kernel(const int* __restrict__ ei, int E) {
    int e = blockIdx.x * blockDim.x + threadIdx.x;
    if (e >= E) return;
    atomicAdd(&g_cnt[ei[E + e]], 1);
}

// single-block warp-shuffle scan -> exclusive rowptr ; also writes dinv
__global__ void scan_kernel(int M) {
    __shared__ int wsum[32];
    __shared__ int carry;
    int t = threadIdx.x, lane = t & 31, w = t >> 5;
    if (t == 0) { carry = 0; g_rowptr[0] = 0; }
    __syncthreads();
    for (int base = 0; base < M; base += 1024) {
        int i = base + t;
        int v = (i < M) ? g_cnt[i] : 0;
        if (i < M) g_dinv[i] = rsqrtf((float)(v + 1));
        int s = v;
        #pragma unroll
        for (int off = 1; off < 32; off <<= 1) {
            int u = __shfl_up_sync(0xFFFFFFFFu, s, off);
            if (lane >= off) s += u;
        }
        if (lane == 31) wsum[w] = s;
        __syncthreads();
        if (w == 0) {
            int ws = wsum[lane];
            #pragma unroll
            for (int off = 1; off < 32; off <<= 1) {
                int u = __shfl_up_sync(0xFFFFFFFFu, ws, off);
                if (lane >= off) ws += u;
            }
            wsum[lane] = ws;
        }
        __syncthreads();
        int add = (w > 0) ? wsum[w - 1] : 0;
        if (i < M) g_rowptr[i + 1] = carry + add + s;
        int total = wsum[31];
        __syncthreads();
        if (t == 0) carry += total;
        __syncthreads();
    }
}

__global__ void fill_kernel(const int* __restrict__ ei, int E) {
    int e = blockIdx.x * blockDim.x + threadIdx.x;
    if (e >= E) return;
    int d = ei[E + e];
    int pos = atomicAdd(&g_fill[d], 1);
    g_csr[g_rowptr[d] + pos] = ei[e];
}

// split all weights to padded bf16 hi/lo planes (K padded to mult-32)
__global__ void prep_kernel(const float* __restrict__ W1, const float* __restrict__ W2,
                            const float* __restrict__ W3, const float* __restrict__ W4) {
    int i = blockIdx.x * blockDim.x + threadIdx.x;
    if (i >= WTOTP) return;
    float v = 0.0f;
    if (i < W2P) {                      // W1 padded: 128 x 512, rows >=100 zero
        int k = i >> 9, n = i & 511;
        if (k < INDIM) v = W1[k * D1 + n];
    } else if (i < W3P) v = W2[i - W2P];
    else if (i < W4P)   v = W3[i - W3P];
    else                v = W4[i - W4P];
    __nv_bfloat16 h = __float2bfloat16_rn(v);
    g_Whi[i] = h;
    g_Wlo[i] = __float2bfloat16_rn(v - __bfloat162float(h));
}

// ---------------------------------------------------------------------------
// Layer-1 gather: fp32 x input, classification fused, sources scaled by dinv[src].
// Output: hi/lo bf16 planes, row stride 128 (cols 100..127 zero).
__global__ __launch_bounds__(256) void gather_x(
    const float* __restrict__ x,
    __nv_bfloat16* __restrict__ Ohi, __nv_bfloat16* __restrict__ Olo,
    const float* __restrict__ nf, int M)
{
    int warp = (blockIdx.x * blockDim.x + threadIdx.x) >> 5;
    int lane = threadIdx.x & 31;
    if (warp >= M) return;
    const int d4 = INDIM / 4;       // 25
    bool p0 = lane < d4;
    int start = g_rowptr[warp], end = g_rowptr[warp + 1];
    float di = g_dinv[warp];

    float4 a0 = make_float4(0.f, 0.f, 0.f, 0.f);
    bool e0 = true, e1 = true, e2 = true;
    if (p0) {
        float4 v = *(const float4*)(x + (size_t)warp * INDIM + lane * 4);
        float4 n0 = *(const float4*)(nf + lane * 4);
        float4 n1 = *(const float4*)(nf + INDIM + lane * 4);
        float4 n2 = *(const float4*)(nf + 2 * INDIM + lane * 4);
        e0 = (v.x == n0.x) && (v.y == n0.y) && (v.z == n0.z) && (v.w == n0.w);
        e1 = (v.x == n1.x) && (v.y == n1.y) && (v.z == n1.z) && (v.w == n1.w);
        e2 = (v.x == n2.x) && (v.y == n2.y) && (v.z == n2.z) && (v.w == n2.w);
        a0.x = di * v.x; a0.y = di * v.y; a0.z = di * v.z; a0.w = di * v.w;
    }
    unsigned m = 0xFFFFFFFFu;
    bool A0 = __all_sync(m, e0);
    bool A1 = __all_sync(m, e1);
    bool A2 = __all_sync(m, e2);
    if (lane == 0) {
        int g = A0 ? 0 : (A1 ? 3 : (A2 ? 1 : 2));
        g_group[warp] = g;
        atomicAdd(&g_gcnt[g], 1.0f);
    }

    int j = start;
    for (; j + 4 <= end; j += 4) {
        int s0 = g_csr[j], s1 = g_csr[j + 1], s2 = g_csr[j + 2], s3 = g_csr[j + 3];
        float d0 = g_dinv[s0], d1 = g_dinv[s1], d2 = g_dinv[s2], d3 = g_dinv[s3];
        if (p0) {
            float4 v0 = *(const float4*)(x + (size_t)s0 * INDIM + lane * 4);
            float4 v1 = *(const float4*)(x + (size_t)s1 * INDIM + lane * 4);
            float4 v2 = *(const float4*)(x + (size_t)s2 * INDIM + lane * 4);
            float4 v3 = *(const float4*)(x + (size_t)s3 * INDIM + lane * 4);
            a0.x += d0 * v0.x + d1 * v1.x + d2 * v2.x + d3 * v3.x;
            a0.y += d0 * v0.y + d1 * v1.y + d2 * v2.y + d3 * v3.y;
            a0.z += d0 * v0.z + d1 * v1.z + d2 * v2.z + d3 * v3.z;
            a0.w += d0 * v0.w + d1 * v1.w + d2 * v2.w + d3 * v3.w;
        }
    }
    for (; j < end; j++) {
        int s = g_csr[j];
        float ds = g_dinv[s];
        if (p0) {
            float4 v = *(const float4*)(x + (size_t)s * INDIM + lane * 4);
            a0.x += ds * v.x; a0.y += ds * v.y; a0.z += ds * v.z; a0.w += ds * v.w;
        }
    }

    float x0 = 0.f, x1 = 0.f, x2 = 0.f, x3 = 0.f;
    if (p0) { x0 = di * a0.x; x1 = di * a0.y; x2 = di * a0.z; x3 = di * a0.w; }
    uint32_t h0 = packb2(x0, x1), h1 = packb2(x2, x3);
    float hx0 = blo(h0), hx1 = bhi(h0), hx2 = blo(h1), hx3 = bhi(h1);
    uint32_t l0 = packb2(x0 - hx0, x1 - hx1), l1 = packb2(x2 - hx2, x3 - hx3);
    size_t ofs = (size_t)warp * 128 + lane * 4;
    *(uint2*)((uint16_t*)Ohi + ofs) = make_uint2(h0, h1);
    *(uint2*)((uint16_t*)Olo + ofs) = make_uint2(l0, l1);
}

// ---------------------------------------------------------------------------
// Packed-plane gather: per-source accumulate hi+lo in fp32.
// epi 0: out = dinv*acc ; epi 1: relu(dinv*acc+b) ; epi 2: relu(dinv*acc+b)*dinv
__device__ __forceinline__ void acc4(const __nv_bfloat16* Hhi, const __nv_bfloat16* Hlo,
                                     size_t ofs, float* a) {
    uint2 u = *(const uint2*)((const uint16_t*)Hhi + ofs);
    uint2 v = *(const uint2*)((const uint16_t*)Hlo + ofs);
    a[0] += blo(u.x) + blo(v.x);
    a[1] += bhi(u.x) + bhi(v.x);
    a[2] += blo(u.y) + blo(v.y);
    a[3] += bhi(u.y) + bhi(v.y);
}

__global__ __launch_bounds__(256) void gather_p(
    const __nv_bfloat16* __restrict__ Hhi, const __nv_bfloat16* __restrict__ Hlo,
    __nv_bfloat16* __restrict__ Ohi, __nv_bfloat16* __restrict__ Olo,
    const float* __restrict__ bias, int M, int dim, int epi)
{
    int warp = (blockIdx.x * blockDim.x + threadIdx.x) >> 5;
    int lane = threadIdx.x & 31;
    if (warp >= M) return;
    int c0 = lane * 4, c1 = c0 + 128;
    bool p1 = c1 < dim;
    int start = g_rowptr[warp], end = g_rowptr[warp + 1];
    float di = g_dinv[warp];

    float a0[4] = {0.f, 0.f, 0.f, 0.f};
    float a1[4] = {0.f, 0.f, 0.f, 0.f};
    size_t selfofs = (size_t)warp * dim;
    acc4(Hhi, Hlo, selfofs + c0, a0);
    if (p1) acc4(Hhi, Hlo, selfofs + c1, a1);

    int j = start;
    for (; j + 4 <= end; j += 4) {
        int s0 = g_csr[j], s1 = g_csr[j + 1], s2 = g_csr[j + 2], s3 = g_csr[j + 3];
        size_t o0 = (size_t)s0 * dim, o1 = (size_t)s1 * dim;
        size_t o2 = (size_t)s2 * dim, o3 = (size_t)s3 * dim;
        acc4(Hhi, Hlo, o0 + c0, a0);
        acc4(Hhi, Hlo, o1 + c0, a0);
        acc4(Hhi, Hlo, o2 + c0, a0);
        acc4(Hhi, Hlo, o3 + c0, a0);
        if (p1) {
            acc4(Hhi, Hlo, o0 + c1, a1);
            acc4(Hhi, Hlo, o1 + c1, a1);
            acc4(Hhi, Hlo, o2 + c1, a1);
            acc4(Hhi, Hlo, o3 + c1, a1);
        }
    }
    for (; j < end; j++) {
        size_t o = (size_t)g_csr[j] * dim;
        acc4(Hhi, Hlo, o + c0, a0);
        if (p1) acc4(Hhi, Hlo, o + c1, a1);
    }

    {
        float vx = di * a0[0], vy = di * a0[1], vz = di * a0[2], vw = di * a0[3];
        if (epi >= 1) {
            float4 b = *(const float4*)(bias + c0);
            vx = fmaxf(vx + b.x, 0.f); vy = fmaxf(vy + b.y, 0.f);
            vz = fmaxf(vz + b.z, 0.f); vw = fmaxf(vw + b.w, 0.f);
            if (epi == 2) { vx *= di; vy *= di; vz *= di; vw *= di; }
        }
        uint32_t h0 = packb2(vx, vy), h1 = packb2(vz, vw);
        uint32_t l0 = packb2(vx - blo(h0), vy - bhi(h0));
        uint32_t l1 = packb2(vz - blo(h1), vw - bhi(h1));
        size_t ofs = (size_t)warp * dim + c0;
        *(uint2*)((uint16_t*)Ohi + ofs) = make_uint2(h0, h1);
        *(uint2*)((uint16_t*)Olo + ofs) = make_uint2(l0, l1);
    }
    if (p1) {
        float vx = di * a1[0], vy = di * a1[1], vz = di * a1[2], vw = di * a1[3];
        if (epi >= 1) {
            float4 b = *(const float4*)(bias + c1);
            vx = fmaxf(vx + b.x, 0.f); vy = fmaxf(vy + b.y, 0.f);
            vz = fmaxf(vz + b.z, 0.f); vw = fmaxf(vw + b.w, 0.f);
            if (epi == 2) { vx *= di; vy *= di; vz *= di; vw *= di; }
        }
        uint32_t h0 = packb2(vx, vy), h1 = packb2(vz, vw);
        uint32_t l0 = packb2(vx - blo(h0), vy - bhi(h0));
        uint32_t l1 = packb2(vz - blo(h1), vw - bhi(h1));
        size_t ofs = (size_t)warp * dim + c1;
        *(uint2*)((uint16_t*)Ohi + ofs) = make_uint2(h0, h1);
        *(uint2*)((uint16_t*)Olo + ofs) = make_uint2(l0, l1);
    }
}

// ---------------------------------------------------------------------------
// Split-BF16 TC GEMM. A and W both pre-split bf16 planes -> all smem fills via
// cp.async. Double-buffered (64KB), ldmatrix + XOR swizzle, m16n8k16, 3-term.
// epi 0: plane relu(acc+bias) ; epi 1: plane dinv*acc ; epi 2: fp32 relu(acc+bias)

__device__ __forceinline__ void mma_bf16(float* c, const uint32_t* a, const uint32_t* b) {
    asm volatile(
        "mma.sync.aligned.m16n8k16.row.col.f32.bf16.bf16.f32 "
        "{%0,%1,%2,%3}, {%4,%5,%6,%7}, {%8,%9}, {%0,%1,%2,%3};\n"
        : "+f"(c[0]), "+f"(c[1]), "+f"(c[2]), "+f"(c[3])
        : "r"(a[0]), "r"(a[1]), "r"(a[2]), "r"(a[3]),
          "r"(b[0]), "r"(b[1]));
}
__device__ __forceinline__ void ldsm_x4(uint32_t* r, uint32_t addr) {
    asm volatile("ldmatrix.sync.aligned.m8n8.x4.shared.b16 {%0,%1,%2,%3}, [%4];"
                 : "=r"(r[0]), "=r"(r[1]), "=r"(r[2]), "=r"(r[3]) : "r"(addr));
}
__device__ __forceinline__ void ldsm_x4_t(uint32_t* r, uint32_t addr) {
    asm volatile("ldmatrix.sync.aligned.m8n8.x4.trans.shared.b16 {%0,%1,%2,%3}, [%4];"
                 : "=r"(r[0]), "=r"(r[1]), "=r"(r[2]), "=r"(r[3]) : "r"(addr));
}

#define GEMM_SMEM 65536

__global__ __launch_bounds__(256, 2) void gemm_bf16s(
    const __nv_bfloat16* __restrict__ Ahi, const __nv_bfloat16* __restrict__ Alo,
    const __nv_bfloat16* __restrict__ Whi, const __nv_bfloat16* __restrict__ Wlo,
    const float* __restrict__ bias,
    __nv_bfloat16* __restrict__ Ohi, __nv_bfloat16* __restrict__ Olo,
    float* __restrict__ Of,
    int M, int K, int N, int epi)
{
    extern __shared__ __align__(16) char smem[];
    // bytes: Ah[2][8192]@0, Al[2][8192]@16384, Bh[2][8192]@32768, Bl[2][8192]@49152
    uint32_t sbase = (uint32_t)__cvta_generic_to_shared(smem);

    int tid = threadIdx.x;
    int r0 = blockIdx.x * 128;
    int n0 = blockIdx.y * 128;
    int wid = tid >> 5, lane = tid & 31;
    int gq = lane >> 2, tq = lane & 3;
    int mwarp = (wid >> 1) * 32;
    int nwarp = (wid & 1) * 64;

    // A loader: thread -> (row, k-half of 16 elems)
    int a_row = tid >> 1, a_h = tid & 1;
    int gr = r0 + a_row;
    bool aok = gr < M;
    int garow = aok ? gr : 0;
    int abytes = aok ? 16 : 0;
    const __nv_bfloat16* pAhi = Ahi + (size_t)garow * K + a_h * 16;
    const __nv_bfloat16* pAlo = Alo + (size_t)garow * K + a_h * 16;
    int aunit0 = a_row * 4 + ((2 * a_h) ^ ((a_row >> 1) & 3));
    int aunit1 = a_row * 4 + ((2 * a_h + 1) ^ ((a_row >> 1) & 3));

    // B loader
    int b_k = tid >> 3, b_g = tid & 7;
    int nb0 = n0 + b_g * 16;
    int bytes0 = (nb0 < N) ? 16 : 0;
    int bytes1 = (nb0 + 8 < N) ? 16 : 0;
    int nbc0 = (nb0 < N) ? nb0 : 0;
    int nbc1 = (nb0 + 8 < N) ? nb0 + 8 : 0;
    int unitB0 = b_k * 16 + ((2 * b_g) ^ (b_k & 7));
    int unitB1 = b_k * 16 + ((2 * b_g + 1) ^ (b_k & 7));

    float acc[2][8][4];
    #pragma unroll
    for (int mi = 0; mi < 2; mi++)
        #pragma unroll
        for (int ni = 0; ni < 8; ni++)
            #pragma unroll
            for (int q = 0; q < 4; q++) acc[mi][ni][q] = 0.0f;

    int nk = K >> 5;

    auto issue = [&](int it, int s) {
        int kt = it * 32;
        uint32_t ah = sbase + s * 8192;
        uint32_t al = sbase + 16384 + s * 8192;
        uint32_t bh = sbase + 32768 + s * 8192;
        uint32_t bl = sbase + 49152 + s * 8192;
        cp16(ah + aunit0 * 16, pAhi + kt, abytes);
        cp16(ah + aunit1 * 16, pAhi + kt + 8, abytes);
        cp16(al + aunit0 * 16, pAlo + kt, abytes);
        cp16(al + aunit1 * 16, pAlo + kt + 8, abytes);
        int kb = kt + b_k;
        const __nv_bfloat16* sh = Whi + (size_t)kb * N;
        const __nv_bfloat16* sl = Wlo + (size_t)kb * N;
        cp16(bh + unitB0 * 16, sh + nbc0, bytes0);
        cp16(bh + unitB1 * 16, sh + nbc1, bytes1);
        cp16(bl + unitB0 * 16, sl + nbc0, bytes0);
        cp16(bl + unitB1 * 16, sl + nbc1, bytes1);
        cp_commit();
    };
    auto compute = [&](int s) {
        uint32_t AhS = sbase + s * 8192;
        uint32_t AlS = sbase + 16384 + s * 8192;
        uint32_t BhS = sbase + 32768 + s * 8192;
        uint32_t BlS = sbase + 49152 + s * 8192;
        #pragma unroll
        for (int ks = 0; ks < 32; ks += 16) {
            uint32_t Ahf[2][4], Alf[2][4];
            #pragma unroll
            for (int mi = 0; mi < 2; mi++) {
                int mrow = mwarp + mi * 16 + (lane & 15);
                int chunk = (ks >> 3) + (lane >> 4);
                int unit = mrow * 4 + (chunk ^ ((mrow >> 1) & 3));
                ldsm_x4(Ahf[mi], AhS + unit * 16);
                ldsm_x4(Alf[mi], AlS + unit * 16);
            }
            #pragma unroll
            for (int p = 0; p < 4; p++) {
                int nbase = nwarp + p * 16;
                int krow = ks + (lane & 7) + ((lane >> 3) & 1) * 8;
                int chunk = (nbase >> 3) + (lane >> 4);
                int unit = krow * 16 + (chunk ^ (krow & 7));
                uint32_t bh[4], bl[4];
                ldsm_x4_t(bh, BhS + unit * 16);
                ldsm_x4_t(bl, BlS + unit * 16);
                #pragma unroll
                for (int half = 0; half < 2; half++) {
                    int ni = 2 * p + half;
                    uint32_t* Bhf = bh + 2 * half;
                    uint32_t* Blf = bl + 2 * half;
                    #pragma unroll
                    for (int mi = 0; mi < 2; mi++) {
                        mma_bf16(acc[mi][ni], Ahf[mi], Bhf);
                        mma_bf16(acc[mi][ni], Ahf[mi], Blf);
                        mma_bf16(acc[mi][ni], Alf[mi], Bhf);
                    }
                }
            }
        }
    };

    issue(0, 0);
    cp_wait0();
    __syncthreads();

    int st = 0;
    for (int it = 0; it < nk; it++) {
        bool more = (it + 1 < nk);
        if (more) issue(it + 1, st ^ 1);
        compute(st);
        if (more) {
            cp_wait0();
            __syncthreads();
            st ^= 1;
        }
    }

    // ---- epilogue
    uint32_t* ohi = (uint32_t*)Ohi;
    uint32_t* olo = (uint32_t*)Olo;
    #pragma unroll
    for (int mi = 0; mi < 2; mi++) {
        int row0 = r0 + mwarp + mi * 16 + gq;
        int row1 = row0 + 8;
        float d0 = 0.f, d1 = 0.f;
        if (epi == 1) {
            if (row0 < M) d0 = g_dinv[row0];
            if (row1 < M) d1 = g_dinv[row1];
        }
        #pragma unroll
        for (int ni = 0; ni < 8; ni++) {
            int col = n0 + nwarp + ni * 8 + 2 * tq;     // always even
            if (col >= N) continue;
            float* c = acc[mi][ni];
            if (epi == 2) {
                float bx = bias[col], by = bias[col + 1];
                if (row0 < M) {
                    Of[(size_t)row0 * N + col]     = fmaxf(c[0] + bx, 0.f);
                    Of[(size_t)row0 * N + col + 1] = fmaxf(c[1] + by, 0.f);
                }
                if (row1 < M) {
                    Of[(size_t)row1 * N + col]     = fmaxf(c[2] + bx, 0.f);
                    Of[(size_t)row1 * N + col + 1] = fmaxf(c[3] + by, 0.f);
                }
            } else {
                float x0, y0, x1, y1;
                if (epi == 0) {
                    float bx = bias[col], by = bias[col + 1];
                    x0 = fmaxf(c[0] + bx, 0.f); y0 = fmaxf(c[1] + by, 0.f);
                    x1 = fmaxf(c[2] + bx, 0.f); y1 = fmaxf(c[3] + by, 0.f);
                } else {
                    x0 = d0 * c[0]; y0 = d0 * c[1];
                    x1 = d1 * c[2]; y1 = d1 * c[3];
                }
                if (row0 < M) {
                    uint32_t h = packb2(x0, y0);
                    uint32_t l = packb2(x0 - blo(h), y0 - bhi(h));
                    size_t idx = ((size_t)row0 * N + col) >> 1;
                    ohi[idx] = h; olo[idx] = l;
                }
                if (row1 < M) {
                    uint32_t h = packb2(x1, y1);
                    uint32_t l = packb2(x1 - blo(h), y1 - bhi(h));
                    size_t idx = ((size_t)row1 * N + col) >> 1;
                    ohi[idx] = h; olo[idx] = l;
                }
            }
        }
    }
}

// ---------------------------------------------------------------------------
// column-parallel grouped sum: grid = D4/4 blocks, warp-shuffle reduce
__global__ void group_reduce(const float* __restrict__ f, int M) {
    int c0 = blockIdx.x * 4;
    int t = threadIdx.x, lane = t & 31;
    float4 s0 = make_float4(0.f, 0.f, 0.f, 0.f);
    float4 s1 = s0, s2 = s0, s3 = s0;
    for (int node = t; node < M; node += blockDim.x) {
        int g = g_group[node];
        float4 v = *(const float4*)(f + (size_t)node * D4 + c0);
        if (g == 0)      { s0.x += v.x; s0.y += v.y; s0.z += v.z; s0.w += v.w; }
        else if (g == 1) { s1.x += v.x; s1.y += v.y; s1.z += v.z; s1.w += v.w; }
        else if (g == 2) { s2.x += v.x; s2.y += v.y; s2.z += v.z; s2.w += v.w; }
        else             { s3.x += v.x; s3.y += v.y; s3.z += v.z; s3.w += v.w; }
    }
    float vals[16] = {s0.x, s0.y, s0.z, s0.w, s1.x, s1.y, s1.z, s1.w,
                      s2.x, s2.y, s2.z, s2.w, s3.x, s3.y, s3.z, s3.w};
    #pragma unroll
    for (int i = 0; i < 16; i++) {
        float v = vals[i];
        #pragma unroll
        for (int off = 16; off; off >>= 1)
            v += __shfl_down_sync(0xFFFFFFFFu, v, off);
        if (lane == 0 && v != 0.0f)
            atomicAdd(&g_gsum[(i >> 2) * D4 + c0 + (i & 3)], v);
    }
}

__global__ void final_out(float* __restrict__ out) {
    int i = blockIdx.x * blockDim.x + threadIdx.x;
    if (i >= 4 * D4) return;
    float c = g_gcnt[i / D4];
    out[i] = (c > 0.0f) ? g_gsum[i] / c : 0.0f;
}

// ---------------------------------------------------------------------------
static inline int ceil_div(long long a, long long b) { return (int)((a + b - 1) / b); }

extern "C" void kernel_launch(void* const* d_in, const int* in_sizes, int n_in,
                              void* d_out, int out_size) {
    const float* x  = (const float*)d_in[0];
    const float* nf = (const float*)d_in[1];
    const int*   ei = (const int*)d_in[2];
    const float* W1 = (const float*)d_in[3];
    const float* b1 = (const float*)d_in[4];
    const float* W2 = (const float*)d_in[5];
    const float* b2 = (const float*)d_in[6];
    const float* W3 = (const float*)d_in[7];
    const float* b3 = (const float*)d_in[8];
    const float* W4 = (const float*)d_in[9];
    const float* b4 = (const float*)d_in[10];
    float* out = (float*)d_out;

    int M = in_sizes[0] / INDIM;     // 50000
    int E = in_sizes[2] / 2;         // 800000

    __nv_bfloat16 *whi, *wlo, *ahi, *alo, *bhi_, *blo_, *chi, *clo;
    float* fout;
    cudaGetSymbolAddress((void**)&whi, g_Whi);
    cudaGetSymbolAddress((void**)&wlo, g_Wlo);
    cudaGetSymbolAddress((void**)&ahi, g_Ahi);
    cudaGetSymbolAddress((void**)&alo, g_Alo);
    cudaGetSymbolAddress((void**)&bhi_, g_Bhi);
    cudaGetSymbolAddress((void**)&blo_, g_Blo);
    cudaGetSymbolAddress((void**)&chi, g_Chi);
    cudaGetSymbolAddress((void**)&clo, g_Clo);
    cudaGetSymbolAddress((void**)&fout, g_fout);

    static int smem_set = 0;
    if (!smem_set) {
        cudaFuncSetAttribute(gemm_bf16s, cudaFuncAttributeMaxDynamicSharedMemorySize, GEMM_SMEM);
        smem_set = 1;
    }

    const int T = 256;
    int gblocks = ceil_div(M, 8);

    // CSR build + dinv + weight split
    zero_kernel<<<ceil_div(M, T), T>>>(M);
    count_kernel<<<ceil_div(E, T), T>>>(ei, E);
    scan_kernel<<<1, 1024>>>(M);
    fill_kernel<<<ceil_div(E, T), T>>>(ei, E);
    prep_kernel<<<ceil_div(WTOTP, T), T>>>(W1, W2, W3, W4);

    // Layer 1: gather (classify fused, pad to K=128) -> GEMM 128->512 epi0
    gather_x<<<gblocks, 256>>>(x, bhi_, blo_, nf, M);
    {
        dim3 g(ceil_div(M, 128), ceil_div(D1, 128));
        gemm_bf16s<<<g, 256, GEMM_SMEM>>>(bhi_, blo_, whi + W1P, wlo + W1P, b1,
                                          chi, clo, nullptr, M, 128, D1, 0);
    }

    // Layer 2: GEMM 512->256 epi1; gather (+b2, relu)
    {
        dim3 g(ceil_div(M, 128), ceil_div(D2, 128));
        gemm_bf16s<<<g, 256, GEMM_SMEM>>>(chi, clo, whi + W2P, wlo + W2P, nullptr,
                                          ahi, alo, nullptr, M, D1, D2, 1);
    }
    gather_p<<<gblocks, 256>>>(ahi, alo, bhi_, blo_, b2, M, D2, 1);

    // Layer 3: GEMM 256->128 epi1; gather (+b3, relu, *dinv)
    {
        dim3 g(ceil_div(M, 128), ceil_div(D3, 128));
        gemm_bf16s<<<g, 256, GEMM_SMEM>>>(bhi_, blo_, whi + W3P, wlo + W3P, nullptr,
                                          ahi, alo, nullptr, M, D2, D3, 1);
    }
    gather_p<<<gblocks, 256>>>(ahi, alo, bhi_, blo_, b3, M, D3, 2);

    // Layer 4: gather agg; GEMM 128->200 epi2 (fp32 + bias + relu)
    gather_p<<<gblocks, 256>>>(bhi_, blo_, ahi, alo, nullptr, M, D3, 0);
    {
        dim3 g(ceil_div(M, 128), ceil_div(D4, 128));
        gemm_bf16s<<<g, 256, GEMM_SMEM>>>(ahi, alo, whi + W4P, wlo + W4P, b4,
                                          nullptr, nullptr, fout, M, D3, D4, 2);
    }

    // pooling
    group_reduce<<<D4 / 4, 256>>>(fout, M);
    final_out<<<ceil_div(4 * D4, T), T>>>(out);
}

// round 11
// speedup vs baseline: 2.0491x; 1.0928x over previous
#include <cuda_runtime.h>
#include <cuda_bf16.h>
#include <cstdint>

#define NMAX    50000
#define EMAX    800000
#define INDIM   100
#define D1      512
#define D2      256
#define D3      128
#define D4      200

// padded (K -> multiple of 32) weight plane offsets, elements
#define W1P     0
#define W2P     65536      // 128*512
#define W3P     196608     // +512*256
#define W4P     229376     // +256*128
#define WTOTP   254976     // +128*200

// Scratch (all device globals are zero-initialized at process start; every
// kernel below restores the zero-state it consumed -> graph replays are
// deterministic)
__device__ float g_dinv[NMAX];
__device__ int   g_group[NMAX];
__device__ float g_gcnt[4];
__device__ float g_gsum[4 * D4];
__device__ int   g_cnt[NMAX];
__device__ int   g_fill[NMAX];
__device__ int   g_rowptr[NMAX + 1];
__device__ int   g_csr[EMAX];
__device__ __align__(16) __nv_bfloat16 g_Whi[WTOTP];
__device__ __align__(16) __nv_bfloat16 g_Wlo[WTOTP];
__device__ __align__(16) __nv_bfloat16 g_Ahi[(size_t)NMAX * 256];
__device__ __align__(16) __nv_bfloat16 g_Alo[(size_t)NMAX * 256];
__device__ __align__(16) __nv_bfloat16 g_Bhi[(size_t)NMAX * 256];
__device__ __align__(16) __nv_bfloat16 g_Blo[(size_t)NMAX * 256];
__device__ __align__(16) __nv_bfloat16 g_Chi[(size_t)NMAX * 512];
__device__ __align__(16) __nv_bfloat16 g_Clo[(size_t)NMAX * 512];
__device__ __align__(16) float g_fout[(size_t)NMAX * D4];

// ---------------------------------------------------------------------------
// helpers
__device__ __forceinline__ uint32_t packb2(float x, float y) {
    uint32_t r;
    asm("cvt.rn.bf16x2.f32 %0, %1, %2;" : "=r"(r) : "f"(y), "f"(x));
    return r;
}
__device__ __forceinline__ float blo(uint32_t u) { return __uint_as_float(u << 16); }
__device__ __forceinline__ float bhi(uint32_t u) { return __uint_as_float(u & 0xFFFF0000u); }

__device__ __forceinline__ void cp16(uint32_t dst, const void* src, int bytes) {
    asm volatile("cp.async.cg.shared.global [%0], [%1], 16, %2;"
                 :: "r"(dst), "l"(src), "r"(bytes));
}
__device__ __forceinline__ void cp_commit() { asm volatile("cp.async.commit_group;"); }
__device__ __forceinline__ void cp_wait0()  { asm volatile("cp.async.wait_group 0;" ::: "memory"); }

// ---------------------------------------------------------------------------
// fused: edge counting (first nCount blocks) + weight splitting (rest)
__global__ void countprep_kernel(const int* __restrict__ ei, int E,
                                 const float* __restrict__ W1, const float* __restrict__ W2,
                                 const float* __restrict__ W3, const float* __restrict__ W4,
                                 int nCount) {
    if ((int)blockIdx.x < nCount) {
        int e = blockIdx.x * blockDim.x + threadIdx.x;
        if (e >= E) return;
        atomicAdd(&g_cnt[ei[E + e]], 1);
    } else {
        int i = (blockIdx.x - nCount) * blockDim.x + threadIdx.x;
        if (i >= WTOTP) return;
        float v = 0.0f;
        if (i < W2P) {                      // W1 padded: 128 x 512, rows >=100 zero
            int k = i >> 9, n = i & 511;
            if (k < INDIM) v = W1[k * D1 + n];
        } else if (i < W3P) v = W2[i - W2P];
        else if (i < W4P)   v = W3[i - W3P];
        else                v = W4[i - W4P];
        __nv_bfloat16 h = __float2bfloat16_rn(v);
        g_Whi[i] = h;
        g_Wlo[i] = __float2bfloat16_rn(v - __bfloat162float(h));
    }
}

// single-block warp-shuffle scan -> exclusive rowptr ; writes dinv ; zeroes g_cnt
__global__ void scan_kernel(int M) {
    __shared__ int wsum[32];
    __shared__ int carry;
    int t = threadIdx.x, lane = t & 31, w = t >> 5;
    if (t == 0) { carry = 0; g_rowptr[0] = 0; }
    __syncthreads();
    for (int base = 0; base < M; base += 1024) {
        int i = base + t;
        int v = (i < M) ? g_cnt[i] : 0;
        if (i < M) {
            g_dinv[i] = rsqrtf((float)(v + 1));
            g_cnt[i] = 0;                     // self-clean for next replay
        }
        int s = v;
        #pragma unroll
        for (int off = 1; off < 32; off <<= 1) {
            int u = __shfl_up_sync(0xFFFFFFFFu, s, off);
            if (lane >= off) s += u;
        }
        if (lane == 31) wsum[w] = s;
        __syncthreads();
        if (w == 0) {
            int ws = wsum[lane];
            #pragma unroll
            for (int off = 1; off < 32; off <<= 1) {
                int u = __shfl_up_sync(0xFFFFFFFFu, ws, off);
                if (lane >= off) ws += u;
            }
            wsum[lane] = ws;
        }
        __syncthreads();
        int add = (w > 0) ? wsum[w - 1] : 0;
        if (i < M) g_rowptr[i + 1] = carry + add + s;
        int total = wsum[31];
        __syncthreads();
        if (t == 0) carry += total;
        __syncthreads();
    }
}

__global__ void fill_kernel(const int* __restrict__ ei, int E) {
    int e = blockIdx.x * blockDim.x + threadIdx.x;
    if (e >= E) return;
    int d = ei[E + e];
    int pos = atomicAdd(&g_fill[d], 1);
    g_csr[g_rowptr[d] + pos] = ei[e];
}

// ---------------------------------------------------------------------------
// Layer-1 gather: fp32 x input, classification fused, sources scaled by dinv[src].
// Output: hi/lo bf16 planes, row stride 128 (cols 100..127 zero). Zeroes g_fill.
__global__ __launch_bounds__(256) void gather_x(
    const float* __restrict__ x,
    __nv_bfloat16* __restrict__ Ohi, __nv_bfloat16* __restrict__ Olo,
    const float* __restrict__ nf, int M)
{
    int warp = (blockIdx.x * blockDim.x + threadIdx.x) >> 5;
    int lane = threadIdx.x & 31;
    if (warp >= M) return;
    const int d4 = INDIM / 4;       // 25
    bool p0 = lane < d4;
    int start = g_rowptr[warp], end = g_rowptr[warp + 1];
    float di = g_dinv[warp];
    if (lane == 0) g_fill[warp] = 0;   // self-clean for next replay

    float4 a0 = make_float4(0.f, 0.f, 0.f, 0.f);
    bool e0 = true, e1 = true, e2 = true;
    if (p0) {
        float4 v = *(const float4*)(x + (size_t)warp * INDIM + lane * 4);
        float4 n0 = *(const float4*)(nf + lane * 4);
        float4 n1 = *(const float4*)(nf + INDIM + lane * 4);
        float4 n2 = *(const float4*)(nf + 2 * INDIM + lane * 4);
        e0 = (v.x == n0.x) && (v.y == n0.y) && (v.z == n0.z) && (v.w == n0.w);
        e1 = (v.x == n1.x) && (v.y == n1.y) && (v.z == n1.z) && (v.w == n1.w);
        e2 = (v.x == n2.x) && (v.y == n2.y) && (v.z == n2.z) && (v.w == n2.w);
        a0.x = di * v.x; a0.y = di * v.y; a0.z = di * v.z; a0.w = di * v.w;
    }
    unsigned m = 0xFFFFFFFFu;
    bool A0 = __all_sync(m, e0);
    bool A1 = __all_sync(m, e1);
    bool A2 = __all_sync(m, e2);
    if (lane == 0) {
        int g = A0 ? 0 : (A1 ? 3 : (A2 ? 1 : 2));
        g_group[warp] = g;
        atomicAdd(&g_gcnt[g], 1.0f);
    }

    int j = start;
    for (; j + 4 <= end; j += 4) {
        int s0 = g_csr[j], s1 = g_csr[j + 1], s2 = g_csr[j + 2], s3 = g_csr[j + 3];
        float d0 = g_dinv[s0], d1 = g_dinv[s1], d2 = g_dinv[s2], d3 = g_dinv[s3];
        if (p0) {
            float4 v0 = *(const float4*)(x + (size_t)s0 * INDIM + lane * 4);
            float4 v1 = *(const float4*)(x + (size_t)s1 * INDIM + lane * 4);
            float4 v2 = *(const float4*)(x + (size_t)s2 * INDIM + lane * 4);
            float4 v3 = *(const float4*)(x + (size_t)s3 * INDIM + lane * 4);
            a0.x += d0 * v0.x + d1 * v1.x + d2 * v2.x + d3 * v3.x;
            a0.y += d0 * v0.y + d1 * v1.y + d2 * v2.y + d3 * v3.y;
            a0.z += d0 * v0.z + d1 * v1.z + d2 * v2.z + d3 * v3.z;
            a0.w += d0 * v0.w + d1 * v1.w + d2 * v2.w + d3 * v3.w;
        }
    }
    for (; j < end; j++) {
        int s = g_csr[j];
        float ds = g_dinv[s];
        if (p0) {
            float4 v = *(const float4*)(x + (size_t)s * INDIM + lane * 4);
            a0.x += ds * v.x; a0.y += ds * v.y; a0.z += ds * v.z; a0.w += ds * v.w;
        }
    }

    float x0 = 0.f, x1 = 0.f, x2 = 0.f, x3 = 0.f;
    if (p0) { x0 = di * a0.x; x1 = di * a0.y; x2 = di * a0.z; x3 = di * a0.w; }
    uint32_t h0 = packb2(x0, x1), h1 = packb2(x2, x3);
    uint32_t l0 = packb2(x0 - blo(h0), x1 - bhi(h0));
    uint32_t l1 = packb2(x2 - blo(h1), x3 - bhi(h1));
    size_t ofs = (size_t)warp * 128 + lane * 4;
    *(uint2*)((uint16_t*)Ohi + ofs) = make_uint2(h0, h1);
    *(uint2*)((uint16_t*)Olo + ofs) = make_uint2(l0, l1);
}

// ---------------------------------------------------------------------------
// dim=256 gather: lane owns 8 columns, 2 x LDG.128 per source row.
// epi 1: out = relu(dinv*acc + bias)
__global__ __launch_bounds__(256) void gather_p256(
    const __nv_bfloat16* __restrict__ Hhi, const __nv_bfloat16* __restrict__ Hlo,
    __nv_bfloat16* __restrict__ Ohi, __nv_bfloat16* __restrict__ Olo,
    const float* __restrict__ bias, int M)
{
    int warp = (blockIdx.x * blockDim.x + threadIdx.x) >> 5;
    int lane = threadIdx.x & 31;
    if (warp >= M) return;
    int c8 = lane * 8;
    const uint16_t* Hh = (const uint16_t*)Hhi;
    const uint16_t* Hl = (const uint16_t*)Hlo;
    int start = g_rowptr[warp], end = g_rowptr[warp + 1];
    float di = g_dinv[warp];

    float a[8] = {0.f, 0.f, 0.f, 0.f, 0.f, 0.f, 0.f, 0.f};
    #define ACC256(h, l) do { \
        a[0] += blo((h).x) + blo((l).x); a[1] += bhi((h).x) + bhi((l).x); \
        a[2] += blo((h).y) + blo((l).y); a[3] += bhi((h).y) + bhi((l).y); \
        a[4] += blo((h).z) + blo((l).z); a[5] += bhi((h).z) + bhi((l).z); \
        a[6] += blo((h).w) + blo((l).w); a[7] += bhi((h).w) + bhi((l).w); } while (0)

    {
        size_t o = (size_t)warp * 256 + c8;
        uint4 h = *(const uint4*)(Hh + o);
        uint4 l = *(const uint4*)(Hl + o);
        ACC256(h, l);
    }
    int j = start;
    for (; j + 4 <= end; j += 4) {
        size_t o0 = (size_t)g_csr[j] * 256 + c8;
        size_t o1 = (size_t)g_csr[j + 1] * 256 + c8;
        size_t o2 = (size_t)g_csr[j + 2] * 256 + c8;
        size_t o3 = (size_t)g_csr[j + 3] * 256 + c8;
        uint4 h0 = *(const uint4*)(Hh + o0), l0 = *(const uint4*)(Hl + o0);
        uint4 h1 = *(const uint4*)(Hh + o1), l1 = *(const uint4*)(Hl + o1);
        uint4 h2 = *(const uint4*)(Hh + o2), l2 = *(const uint4*)(Hl + o2);
        uint4 h3 = *(const uint4*)(Hh + o3), l3 = *(const uint4*)(Hl + o3);
        ACC256(h0, l0); ACC256(h1, l1); ACC256(h2, l2); ACC256(h3, l3);
    }
    for (; j < end; j++) {
        size_t o = (size_t)g_csr[j] * 256 + c8;
        uint4 h = *(const uint4*)(Hh + o);
        uint4 l = *(const uint4*)(Hl + o);
        ACC256(h, l);
    }
    #undef ACC256

    float4 b0 = *(const float4*)(bias + c8);
    float4 b1 = *(const float4*)(bias + c8 + 4);
    float v0 = fmaxf(di * a[0] + b0.x, 0.f), v1 = fmaxf(di * a[1] + b0.y, 0.f);
    float v2 = fmaxf(di * a[2] + b0.z, 0.f), v3 = fmaxf(di * a[3] + b0.w, 0.f);
    float v4 = fmaxf(di * a[4] + b1.x, 0.f), v5 = fmaxf(di * a[5] + b1.y, 0.f);
    float v6 = fmaxf(di * a[6] + b1.z, 0.f), v7 = fmaxf(di * a[7] + b1.w, 0.f);
    uint4 hv, lv;
    hv.x = packb2(v0, v1); lv.x = packb2(v0 - blo(hv.x), v1 - bhi(hv.x));
    hv.y = packb2(v2, v3); lv.y = packb2(v2 - blo(hv.y), v3 - bhi(hv.y));
    hv.z = packb2(v4, v5); lv.z = packb2(v4 - blo(hv.z), v5 - bhi(hv.z));
    hv.w = packb2(v6, v7); lv.w = packb2(v6 - blo(hv.w), v7 - bhi(hv.w));
    size_t o = (size_t)warp * 256 + c8;
    *(uint4*)((uint16_t*)Ohi + o) = hv;
    *(uint4*)((uint16_t*)Olo + o) = lv;
}

// dim=128 gather: lanes 0-15 scan hi plane, lanes 16-31 scan lo plane,
// 1 x LDG.128 per lane per row, shfl-merge at the end.
// epi 0: out = dinv*acc ; epi 2: out = relu(dinv*acc + bias) * dinv
__global__ __launch_bounds__(256) void gather_p128(
    const __nv_bfloat16* __restrict__ Hhi, const __nv_bfloat16* __restrict__ Hlo,
    __nv_bfloat16* __restrict__ Ohi, __nv_bfloat16* __restrict__ Olo,
    const float* __restrict__ bias, int M, int epi)
{
    int warp = (blockIdx.x * blockDim.x + threadIdx.x) >> 5;
    int lane = threadIdx.x & 31;
    if (warp >= M) return;
    int cq = (lane & 15) * 8;
    const uint16_t* P = (lane < 16) ? (const uint16_t*)Hhi : (const uint16_t*)Hlo;
    int start = g_rowptr[warp], end = g_rowptr[warp + 1];
    float di = g_dinv[warp];

    float a[8] = {0.f, 0.f, 0.f, 0.f, 0.f, 0.f, 0.f, 0.f};
    #define ACC128(u) do { \
        a[0] += blo((u).x); a[1] += bhi((u).x); \
        a[2] += blo((u).y); a[3] += bhi((u).y); \
        a[4] += blo((u).z); a[5] += bhi((u).z); \
        a[6] += blo((u).w); a[7] += bhi((u).w); } while (0)

    {
        uint4 u = *(const uint4*)(P + (size_t)warp * 128 + cq);
        ACC128(u);
    }
    int j = start;
    for (; j + 4 <= end; j += 4) {
        uint4 u0 = *(const uint4*)(P + (size_t)g_csr[j] * 128 + cq);
        uint4 u1 = *(const uint4*)(P + (size_t)g_csr[j + 1] * 128 + cq);
        uint4 u2 = *(const uint4*)(P + (size_t)g_csr[j + 2] * 128 + cq);
        uint4 u3 = *(const uint4*)(P + (size_t)g_csr[j + 3] * 128 + cq);
        ACC128(u0); ACC128(u1); ACC128(u2); ACC128(u3);
    }
    for (; j < end; j++) {
        uint4 u = *(const uint4*)(P + (size_t)g_csr[j] * 128 + cq);
        ACC128(u);
    }
    #undef ACC128

    // merge lo-plane partials (lanes 16-31) into hi lanes (0-15)
    #pragma unroll
    for (int q = 0; q < 8; q++)
        a[q] += __shfl_down_sync(0xFFFFFFFFu, a[q], 16);

    if (lane < 16) {
        float v[8];
        if (epi == 2) {
            float4 b0 = *(const float4*)(bias + cq);
            float4 b1 = *(const float4*)(bias + cq + 4);
            v[0] = fmaxf(di * a[0] + b0.x, 0.f) * di;
            v[1] = fmaxf(di * a[1] + b0.y, 0.f) * di;
            v[2] = fmaxf(di * a[2] + b0.z, 0.f) * di;
            v[3] = fmaxf(di * a[3] + b0.w, 0.f) * di;
            v[4] = fmaxf(di * a[4] + b1.x, 0.f) * di;
            v[5] = fmaxf(di * a[5] + b1.y, 0.f) * di;
            v[6] = fmaxf(di * a[6] + b1.z, 0.f) * di;
            v[7] = fmaxf(di * a[7] + b1.w, 0.f) * di;
        } else {
            #pragma unroll
            for (int q = 0; q < 8; q++) v[q] = di * a[q];
        }
        uint4 hv, lv;
        hv.x = packb2(v[0], v[1]); lv.x = packb2(v[0] - blo(hv.x), v[1] - bhi(hv.x));
        hv.y = packb2(v[2], v[3]); lv.y = packb2(v[2] - blo(hv.y), v[3] - bhi(hv.y));
        hv.z = packb2(v[4], v[5]); lv.z = packb2(v[4] - blo(hv.z), v[5] - bhi(hv.z));
        hv.w = packb2(v[6], v[7]); lv.w = packb2(v[6] - blo(hv.w), v[7] - bhi(hv.w));
        size_t o = (size_t)warp * 128 + cq;
        *(uint4*)((uint16_t*)Ohi + o) = hv;
        *(uint4*)((uint16_t*)Olo + o) = lv;
    }
}

// ---------------------------------------------------------------------------
// Split-BF16 TC GEMM (unchanged from R10): cp.async both operands, double
// buffer, ldmatrix + XOR swizzle, m16n8k16, 3-term compensation.
__device__ __forceinline__ void mma_bf16(float* c, const uint32_t* a, const uint32_t* b) {
    asm volatile(
        "mma.sync.aligned.m16n8k16.row.col.f32.bf16.bf16.f32 "
        "{%0,%1,%2,%3}, {%4,%5,%6,%7}, {%8,%9}, {%0,%1,%2,%3};\n"
        : "+f"(c[0]), "+f"(c[1]), "+f"(c[2]), "+f"(c[3])
        : "r"(a[0]), "r"(a[1]), "r"(a[2]), "r"(a[3]),
          "r"(b[0]), "r"(b[1]));
}
__device__ __forceinline__ void ldsm_x4(uint32_t* r, uint32_t addr) {
    asm volatile("ldmatrix.sync.aligned.m8n8.x4.shared.b16 {%0,%1,%2,%3}, [%4];"
                 : "=r"(r[0]), "=r"(r[1]), "=r"(r[2]), "=r"(r[3]) : "r"(addr));
}
__device__ __forceinline__ void ldsm_x4_t(uint32_t* r, uint32_t addr) {
    asm volatile("ldmatrix.sync.aligned.m8n8.x4.trans.shared.b16 {%0,%1,%2,%3}, [%4];"
                 : "=r"(r[0]), "=r"(r[1]), "=r"(r[2]), "=r"(r[3]) : "r"(addr));
}

#define GEMM_SMEM 65536

__global__ __launch_bounds__(256, 2) void gemm_bf16s(
    const __nv_bfloat16* __restrict__ Ahi, const __nv_bfloat16* __restrict__ Alo,
    const __nv_bfloat16* __restrict__ Whi, const __nv_bfloat16* __restrict__ Wlo,
    const float* __restrict__ bias,
    __nv_bfloat16* __restrict__ Ohi, __nv_bfloat16* __restrict__ Olo,
    float* __restrict__ Of,
    int M, int K, int N, int epi)
{
    extern __shared__ __align__(16) char smem[];
    uint32_t sbase = (uint32_t)__cvta_generic_to_shared(smem);

    int tid = threadIdx.x;
    int r0 = blockIdx.x * 128;
    int n0 = blockIdx.y * 128;
    int wid = tid >> 5, lane = tid & 31;
    int gq = lane >> 2, tq = lane & 3;
    int mwarp = (wid >> 1) * 32;
    int nwarp = (wid & 1) * 64;

    int a_row = tid >> 1, a_h = tid & 1;
    int gr = r0 + a_row;
    bool aok = gr < M;
    int garow = aok ? gr : 0;
    int abytes = aok ? 16 : 0;
    const __nv_bfloat16* pAhi = Ahi + (size_t)garow * K + a_h * 16;
    const __nv_bfloat16* pAlo = Alo + (size_t)garow * K + a_h * 16;
    int aunit0 = a_row * 4 + ((2 * a_h) ^ ((a_row >> 1) & 3));
    int aunit1 = a_row * 4 + ((2 * a_h + 1) ^ ((a_row >> 1) & 3));

    int b_k = tid >> 3, b_g = tid & 7;
    int nb0 = n0 + b_g * 16;
    int bytes0 = (nb0 < N) ? 16 : 0;
    int bytes1 = (nb0 + 8 < N) ? 16 : 0;
    int nbc0 = (nb0 < N) ? nb0 : 0;
    int nbc1 = (nb0 + 8 < N) ? nb0 + 8 : 0;
    int unitB0 = b_k * 16 + ((2 * b_g) ^ (b_k & 7));
    int unitB1 = b_k * 16 + ((2 * b_g + 1) ^ (b_k & 7));

    float acc[2][8][4];
    #pragma unroll
    for (int mi = 0; mi < 2; mi++)
        #pragma unroll
        for (int ni = 0; ni < 8; ni++)
            #pragma unroll
            for (int q = 0; q < 4; q++) acc[mi][ni][q] = 0.0f;

    int nk = K >> 5;

    auto issue = [&](int it, int s) {
        int kt = it * 32;
        uint32_t ah = sbase + s * 8192;
        uint32_t al = sbase + 16384 + s * 8192;
        uint32_t bh = sbase + 32768 + s * 8192;
        uint32_t bl = sbase + 49152 + s * 8192;
        cp16(ah + aunit0 * 16, pAhi + kt, abytes);
        cp16(ah + aunit1 * 16, pAhi + kt + 8, abytes);
        cp16(al + aunit0 * 16, pAlo + kt, abytes);
        cp16(al + aunit1 * 16, pAlo + kt + 8, abytes);
        int kb = kt + b_k;
        const __nv_bfloat16* sh = Whi + (size_t)kb * N;
        const __nv_bfloat16* sl = Wlo + (size_t)kb * N;
        cp16(bh + unitB0 * 16, sh + nbc0, bytes0);
        cp16(bh + unitB1 * 16, sh + nbc1, bytes1);
        cp16(bl + unitB0 * 16, sl + nbc0, bytes0);
        cp16(bl + unitB1 * 16, sl + nbc1, bytes1);
        cp_commit();
    };
    auto compute = [&](int s) {
        uint32_t AhS = sbase + s * 8192;
        uint32_t AlS = sbase + 16384 + s * 8192;
        uint32_t BhS = sbase + 32768 + s * 8192;
        uint32_t BlS = sbase + 49152 + s * 8192;
        #pragma unroll
        for (int ks = 0; ks < 32; ks += 16) {
            uint32_t Ahf[2][4], Alf[2][4];
            #pragma unroll
            for (int mi = 0; mi < 2; mi++) {
                int mrow = mwarp + mi * 16 + (lane & 15);
                int chunk = (ks >> 3) + (lane >> 4);
                int unit = mrow * 4 + (chunk ^ ((mrow >> 1) & 3));
                ldsm_x4(Ahf[mi], AhS + unit * 16);
                ldsm_x4(Alf[mi], AlS + unit * 16);
            }
            #pragma unroll
            for (int p = 0; p < 4; p++) {
                int nbase = nwarp + p * 16;
                int krow = ks + (lane & 7) + ((lane >> 3) & 1) * 8;
                int chunk = (nbase >> 3) + (lane >> 4);
                int unit = krow * 16 + (chunk ^ (krow & 7));
                uint32_t bh[4], bl[4];
                ldsm_x4_t(bh, BhS + unit * 16);
                ldsm_x4_t(bl, BlS + unit * 16);
                #pragma unroll
                for (int half = 0; half < 2; half++) {
                    int ni = 2 * p + half;
                    uint32_t* Bhf = bh + 2 * half;
                    uint32_t* Blf = bl + 2 * half;
                    #pragma unroll
                    for (int mi = 0; mi < 2; mi++) {
                        mma_bf16(acc[mi][ni], Ahf[mi], Bhf);
                        mma_bf16(acc[mi][ni], Ahf[mi], Blf);
                        mma_bf16(acc[mi][ni], Alf[mi], Bhf);
                    }
                }
            }
        }
    };

    issue(0, 0);
    cp_wait0();
    __syncthreads();

    int st = 0;
    for (int it = 0; it < nk; it++) {
        bool more = (it + 1 < nk);
        if (more) issue(it + 1, st ^ 1);
        compute(st);
        if (more) {
            cp_wait0();
            __syncthreads();
            st ^= 1;
        }
    }

    uint32_t* ohi = (uint32_t*)Ohi;
    uint32_t* olo = (uint32_t*)Olo;
    #pragma unroll
    for (int mi = 0; mi < 2; mi++) {
        int row0 = r0 + mwarp + mi * 16 + gq;
        int row1 = row0 + 8;
        float d0 = 0.f, d1 = 0.f;
        if (epi == 1) {
            if (row0 < M) d0 = g_dinv[row0];
            if (row1 < M) d1 = g_dinv[row1];
        }
        #pragma unroll
        for (int ni = 0; ni < 8; ni++) {
            int col = n0 + nwarp + ni * 8 + 2 * tq;
            if (col >= N) continue;
            float* c = acc[mi][ni];
            if (epi == 2) {
                float bx = bias[col], by = bias[col + 1];
                if (row0 < M) {
                    Of[(size_t)row0 * N + col]     = fmaxf(c[0] + bx, 0.f);
                    Of[(size_t)row0 * N + col + 1] = fmaxf(c[1] + by, 0.f);
                }
                if (row1 < M) {
                    Of[(size_t)row1 * N + col]     = fmaxf(c[2] + bx, 0.f);
                    Of[(size_t)row1 * N + col + 1] = fmaxf(c[3] + by, 0.f);
                }
            } else {
                float x0, y0, x1, y1;
                if (epi == 0) {
                    float bx = bias[col], by = bias[col + 1];
                    x0 = fmaxf(c[0] + bx, 0.f); y0 = fmaxf(c[1] + by, 0.f);
                    x1 = fmaxf(c[2] + bx, 0.f); y1 = fmaxf(c[3] + by, 0.f);
                } else {
                    x0 = d0 * c[0]; y0 = d0 * c[1];
                    x1 = d1 * c[2]; y1 = d1 * c[3];
                }
                if (row0 < M) {
                    uint32_t h = packb2(x0, y0);
                    uint32_t l = packb2(x0 - blo(h), y0 - bhi(h));
                    size_t idx = ((size_t)row0 * N + col) >> 1;
                    ohi[idx] = h; olo[idx] = l;
                }
                if (row1 < M) {
                    uint32_t h = packb2(x1, y1);
                    uint32_t l = packb2(x1 - blo(h), y1 - bhi(h));
                    size_t idx = ((size_t)row1 * N + col) >> 1;
                    ohi[idx] = h; olo[idx] = l;
                }
            }
        }
    }
}

// ---------------------------------------------------------------------------
// column-parallel grouped sum
__global__ void group_reduce(const float* __restrict__ f, int M) {
    int c0 = blockIdx.x * 4;
    int t = threadIdx.x, lane = t & 31;
    float4 s0 = make_float4(0.f, 0.f, 0.f, 0.f);
    float4 s1 = s0, s2 = s0, s3 = s0;
    for (int node = t; node < M; node += blockDim.x) {
        int g = g_group[node];
        float4 v = *(const float4*)(f + (size_t)node * D4 + c0);
        if (g == 0)      { s0.x += v.x; s0.y += v.y; s0.z += v.z; s0.w += v.w; }
        else if (g == 1) { s1.x += v.x; s1.y += v.y; s1.z += v.z; s1.w += v.w; }
        else if (g == 2) { s2.x += v.x; s2.y += v.y; s2.z += v.z; s2.w += v.w; }
        else             { s3.x += v.x; s3.y += v.y; s3.z += v.z; s3.w += v.w; }
    }
    float vals[16] = {s0.x, s0.y, s0.z, s0.w, s1.x, s1.y, s1.z, s1.w,
                      s2.x, s2.y, s2.z, s2.w, s3.x, s3.y, s3.z, s3.w};
    #pragma unroll
    for (int i = 0; i < 16; i++) {
        float v = vals[i];
        #pragma unroll
        for (int off = 16; off; off >>= 1)
            v += __shfl_down_sync(0xFFFFFFFFu, v, off);
        if (lane == 0 && v != 0.0f)
            atomicAdd(&g_gsum[(i >> 2) * D4 + c0 + (i & 3)], v);
    }
}

// single block: write result, then self-clean g_gsum / g_gcnt
__global__ void final_out(float* __restrict__ out) {
    int i = threadIdx.x;
    if (i < 4 * D4) {
        float c = g_gcnt[i / D4];
        out[i] = (c > 0.0f) ? g_gsum[i] / c : 0.0f;
    }
    __syncthreads();
    if (i < 4 * D4) g_gsum[i] = 0.0f;
    if (i < 4) g_gcnt[i] = 0.0f;
}

// ---------------------------------------------------------------------------
static inline int ceil_div(long long a, long long b) { return (int)((a + b - 1) / b); }

extern "C" void kernel_launch(void* const* d_in, const int* in_sizes, int n_in,
                              void* d_out, int out_size) {
    const float* x  = (const float*)d_in[0];
    const float* nf = (const float*)d_in[1];
    const int*   ei = (const int*)d_in[2];
    const float* W1 = (const float*)d_in[3];
    const float* b1 = (const float*)d_in[4];
    const float* W2 = (const float*)d_in[5];
    const float* b2 = (const float*)d_in[6];
    const float* W3 = (const float*)d_in[7];
    const float* b3 = (const float*)d_in[8];
    const float* W4 = (const float*)d_in[9];
    const float* b4 = (const float*)d_in[10];
    float* out = (float*)d_out;

    int M = in_sizes[0] / INDIM;     // 50000
    int E = in_sizes[2] / 2;         // 800000

    __nv_bfloat16 *whi, *wlo, *ahi, *alo, *bhi_, *blo_, *chi, *clo;
    float* fout;
    cudaGetSymbolAddress((void**)&whi, g_Whi);
    cudaGetSymbolAddress((void**)&wlo, g_Wlo);
    cudaGetSymbolAddress((void**)&ahi, g_Ahi);
    cudaGetSymbolAddress((void**)&alo, g_Alo);
    cudaGetSymbolAddress((void**)&bhi_, g_Bhi);
    cudaGetSymbolAddress((void**)&blo_, g_Blo);
    cudaGetSymbolAddress((void**)&chi, g_Chi);
    cudaGetSymbolAddress((void**)&clo, g_Clo);
    cudaGetSymbolAddress((void**)&fout, g_fout);

    static int smem_set = 0;
    if (!smem_set) {
        cudaFuncSetAttribute(gemm_bf16s, cudaFuncAttributeMaxDynamicSharedMemorySize, GEMM_SMEM);
        smem_set = 1;
    }

    const int T = 256;
    int gblocks = ceil_div(M, 8);
    int nCount = ceil_div(E, T);
    int nPrep  = ceil_div(WTOTP, T);

    // 0: count edges + split weights (fused, disjoint blocks)
    countprep_kernel<<<nCount + nPrep, T>>>(ei, E, W1, W2, W3, W4, nCount);
    // 1: scan -> rowptr (+dinv, self-clean g_cnt)
    scan_kernel<<<1, 1024>>>(M);
    // 2: CSR fill
    fill_kernel<<<ceil_div(E, T), T>>>(ei, E);
    // 3: Layer-1 gather (classify fused, self-clean g_fill)   <- ncu slot
    gather_x<<<gblocks, 256>>>(x, bhi_, blo_, nf, M);

    // Layer 1 GEMM 128->512 epi0
    {
        dim3 g(ceil_div(M, 128), ceil_div(D1, 128));
        gemm_bf16s<<<g, 256, GEMM_SMEM>>>(bhi_, blo_, whi + W1P, wlo + W1P, b1,
                                          chi, clo, nullptr, M, 128, D1, 0);
    }
    // Layer 2: GEMM 512->256 epi1; gather256 (+b2, relu)
    {
        dim3 g(ceil_div(M, 128), ceil_div(D2, 128));
        gemm_bf16s<<<g, 256, GEMM_SMEM>>>(chi, clo, whi + W2P, wlo + W2P, nullptr,
                                          ahi, alo, nullptr, M, D1, D2, 1);
    }
    gather_p256<<<gblocks, 256>>>(ahi, alo, bhi_, blo_, b2, M);

    // Layer 3: GEMM 256->128 epi1; gather128 (+b3, relu, *dinv)
    {
        dim3 g(ceil_div(M, 128), ceil_div(D3, 128));
        gemm_bf16s<<<g, 256, GEMM_SMEM>>>(bhi_, blo_, whi + W3P, wlo + W3P, nullptr,
                                          ahi, alo, nullptr, M, D2, D3, 1);
    }
    gather_p128<<<gblocks, 256>>>(ahi, alo, bhi_, blo_, b3, M, 2);

    // Layer 4: gather128 agg; GEMM 128->200 epi2 (fp32 + bias + relu)
    gather_p128<<<gblocks, 256>>>(bhi_, blo_, ahi, alo, nullptr, M, 0);
    {
        dim3 g(ceil_div(M, 128), ceil_div(D4, 128));
        gemm_bf16s<<<g, 256, GEMM_SMEM>>>(ahi, alo, whi + W4P, wlo + W4P, b4,
                                          nullptr, nullptr, fout, M, D3, D4, 2);
    }

    // pooling (self-cleaning final_out)
    group_reduce<<<D4 / 4, 256>>>(fout, M);
    final_out<<<1, 800>>>(out);
}